// round 12
// baseline (speedup 1.0000x reference)
#include <cuda_runtime.h>
#include <cuda_fp16.h>
#include <cstdint>

#define H   8
#define Dd  32
#define HD  256
#define NC  10000
#define NS  1024
#define INC 128
#define INS 64
#define ECC 120000
#define ECS 10000
#define LALPHA 0.2f
#define NEG_BIG -1e30f
#define KAGG 384   // 3 relations x 128 feature dims

// ---------------- device scratch (static; no runtime allocation) ----------------
__device__ __half g_Wh_in[NS * HD];                       // state self projection
__device__ __half g_agg_c[(size_t)24 * NC * KAGG];        // [dst_type*8+h][node][384], 184 MB
__device__ __half g_agg_s[(size_t)8 * NS * KAGG];         // [h][node][384]

__device__ float g_as_cc[9 * NC * H];
__device__ float g_ad_cc[9 * NC * H];
__device__ float g_as_cs[3 * NC * H];
__device__ float g_ad_s[3 * NS * H];

__device__ float g_asmax[12 * H];

__device__ float g_wred_as[9 * INC * H];
__device__ float g_wred_ad[9 * INC * H];
__device__ float g_wred_as_cs[3 * INC * H];
__device__ float g_wred_ad_s[3 * INS * H];
__device__ float g_bred_as[9 * H];
__device__ float g_bred_ad[9 * H];
__device__ float g_bred_as_cs[3 * H];
__device__ float g_bred_ad_s[3 * H];

__device__ int g_cnt_cc[9 * NC];
__device__ int g_off_cc[9 * NC];
__device__ int g_cur_cc[9 * NC];
__device__ int g_csr_cc[9 * ECC];
__device__ int g_cnt_cs[3 * NS];
__device__ int g_off_cs[3 * NS];
__device__ int g_cur_cs[3 * NS];
__device__ int g_csr_cs[3 * ECS];

// ---------------- zero counters ----------------
__global__ void k_zero_counters() {
    int i = blockIdx.x * blockDim.x + threadIdx.x;
    if (i < 9 * NC) g_cnt_cc[i] = 0;
    if (i < 3 * NS) g_cnt_cs[i] = 0;
}

// ---------------- reduce attention vectors into weights ----------------
__global__ void k_wred(const float* __restrict__ W_node, const float* __restrict__ b_node,
                       const float* __restrict__ W_cc,   const float* __restrict__ b_cc,
                       const float* __restrict__ W_cs,   const float* __restrict__ b_cs,
                       const float* __restrict__ W_in,   const float* __restrict__ b_in,
                       const float* __restrict__ attn_cc, const float* __restrict__ attn_cs) {
    int gid = blockIdx.x * blockDim.x + threadIdx.x;
    if (gid >= 24 * INC * H) return;
    int j   = gid / (INC * H);
    int rem = gid % (INC * H);
    int k = rem / H, h = rem % H;
    const float *Wsrc, *att, *bvec;
    float *dst, *bdst;
    int Kin = INC;
    if (j < 9) {
        Wsrc = W_cc + (size_t)j * INC * HD;
        att  = attn_cc + (size_t)(j * 2 + 0) * HD;
        bvec = b_cc + (size_t)j * HD;
        dst  = g_wred_as + j * INC * H; bdst = g_bred_as + j * H;
    } else if (j < 18) {
        int r = j - 9;
        Wsrc = W_node + (size_t)(r % 3) * INC * HD;
        att  = attn_cc + (size_t)(r * 2 + 1) * HD;
        bvec = b_node + (size_t)(r % 3) * HD;
        dst  = g_wred_ad + r * INC * H; bdst = g_bred_ad + r * H;
    } else if (j < 21) {
        int t = j - 18;
        Wsrc = W_cs + (size_t)t * INC * HD;
        att  = attn_cs + (size_t)(t * 2 + 0) * HD;
        bvec = b_cs + (size_t)t * HD;
        dst  = g_wred_as_cs + t * INC * H; bdst = g_bred_as_cs + t * H;
    } else {
        int t = j - 21;
        Wsrc = W_in;
        att  = attn_cs + (size_t)(t * 2 + 1) * HD;
        bvec = b_in;
        dst  = g_wred_ad_s + t * INS * H; bdst = g_bred_ad_s + t * H;
        Kin = INS;
    }
    if (k >= Kin) return;
    float s = 0.f;
    #pragma unroll
    for (int d = 0; d < Dd; d++)
        s += Wsrc[(size_t)k * HD + h * Dd + d] * att[h * Dd + d];
    dst[k * H + h] = s;
    if (k == 0) {
        float bs = 0.f;
        #pragma unroll
        for (int d = 0; d < Dd; d++) bs += bvec[h * Dd + d] * att[h * Dd + d];
        bdst[h] = bs;
    }
}

// ---------------- fused skinny GEMMs: one pass over each node type ----------
__global__ void __launch_bounds__(256) k_skinny(const float* __restrict__ f1,
                                                const float* __restrict__ f2,
                                                const float* __restrict__ f3,
                                                const float* __restrict__ fs) {
    int t = blockIdx.y;
    __shared__ float Ws[7][H][INC];
    __shared__ float bsm[7][H];
    __shared__ const float* wptr[7];
    __shared__ float* optr[7];
    __shared__ const float* bptr[7];

    int Kin = (t < 3) ? INC : INS;
    int nG  = (t < 3) ? 7 : 3;
    int nNodes = (t < 3) ? NC : NS;
    const float* feat = (t == 0) ? f1 : (t == 1) ? f2 : (t == 2) ? f3 : fs;

    if (threadIdx.x < (unsigned)nG) {
        int g = threadIdx.x;
        if (t < 3) {
            if (g < 3) {
                int r = t * 3 + g;
                wptr[g] = g_wred_as + r * INC * H;
                bptr[g] = g_bred_as + r * H;
                optr[g] = g_as_cc + (size_t)r * NC * H;
            } else if (g < 6) {
                int r = (g - 3) * 3 + t;
                wptr[g] = g_wred_ad + r * INC * H;
                bptr[g] = g_bred_ad + r * H;
                optr[g] = g_ad_cc + (size_t)r * NC * H;
            } else {
                wptr[g] = g_wred_as_cs + t * INC * H;
                bptr[g] = g_bred_as_cs + t * H;
                optr[g] = g_as_cs + (size_t)t * NC * H;
            }
        } else {
            wptr[g] = g_wred_ad_s + g * INS * H;
            bptr[g] = g_bred_ad_s + g * H;
            optr[g] = g_ad_s + (size_t)g * NS * H;
        }
    }
    __syncthreads();

    for (int idx = threadIdx.x; idx < nG * H * Kin; idx += 256) {
        int g = idx / (H * Kin);
        int rem = idx % (H * Kin);
        int h = rem / Kin, k = rem % Kin;
        Ws[g][h][k] = wptr[g][k * H + h];
    }
    if (threadIdx.x < (unsigned)(nG * H)) {
        int g = threadIdx.x / H, h = threadIdx.x % H;
        bsm[g][h] = bptr[g][h];
    }
    __syncthreads();

    int warp = threadIdx.x >> 5, lane = threadIdx.x & 31;
    int node = blockIdx.x * 8 + warp;
    if (node >= nNodes) return;
    const float* frow = feat + (size_t)node * Kin;
    float f[4];
    int nc = Kin / 32;
    for (int c = 0; c < nc; c++) f[c] = frow[c * 32 + lane];

    for (int g = 0; g < nG; g++) {
        float mine = 0.f;
        #pragma unroll
        for (int h = 0; h < H; h++) {
            float v = 0.f;
            for (int c = 0; c < nc; c++) v += f[c] * Ws[g][h][c * 32 + lane];
            #pragma unroll
            for (int o = 16; o > 0; o >>= 1) v += __shfl_xor_sync(0xffffffffu, v, o);
            if (lane == h) mine = v;
        }
        if (lane < H) optr[g][(size_t)node * H + lane] = mine + bsm[g][lane];
    }
}

// ---------------- per-relation a_src max (for single-pass softmax) ----------
__global__ void __launch_bounds__(256) k_asmax() {
    int rel = blockIdx.x;
    const float* asb = (rel < 9) ? (g_as_cc + (size_t)rel * NC * H)
                                 : (g_as_cs + (size_t)(rel - 9) * NC * H);
    float mx[H];
    #pragma unroll
    for (int h = 0; h < H; h++) mx[h] = NEG_BIG;
    for (int i = threadIdx.x; i < NC; i += 256) {
        float4 a0 = *(const float4*)(asb + (size_t)i * H);
        float4 a1 = *(const float4*)(asb + (size_t)i * H + 4);
        mx[0]=fmaxf(mx[0],a0.x); mx[1]=fmaxf(mx[1],a0.y); mx[2]=fmaxf(mx[2],a0.z); mx[3]=fmaxf(mx[3],a0.w);
        mx[4]=fmaxf(mx[4],a1.x); mx[5]=fmaxf(mx[5],a1.y); mx[6]=fmaxf(mx[6],a1.z); mx[7]=fmaxf(mx[7],a1.w);
    }
    #pragma unroll
    for (int h = 0; h < H; h++)
        #pragma unroll
        for (int o = 16; o > 0; o >>= 1) mx[h] = fmaxf(mx[h], __shfl_xor_sync(0xffffffffu, mx[h], o));
    __shared__ float sm[8][H];
    int warp = threadIdx.x >> 5, lane = threadIdx.x & 31;
    if (lane == 0)
        #pragma unroll
        for (int h = 0; h < H; h++) sm[warp][h] = mx[h];
    __syncthreads();
    if (threadIdx.x < H) {
        float v = sm[0][threadIdx.x];
        #pragma unroll
        for (int w = 1; w < 8; w++) v = fmaxf(v, sm[w][threadIdx.x]);
        g_asmax[rel * H + threadIdx.x] = v;
    }
}

// ---------------- FP16 HMMA helper ----------------
__device__ __forceinline__ void mma_f16(float c[4], const unsigned a[4], const unsigned b[2]) {
    asm volatile("mma.sync.aligned.m16n8k16.row.col.f32.f16.f16.f32 "
        "{%0,%1,%2,%3}, {%4,%5,%6,%7}, {%8,%9}, {%0,%1,%2,%3};"
        : "+f"(c[0]), "+f"(c[1]), "+f"(c[2]), "+f"(c[3])
        : "r"(a[0]), "r"(a[1]), "r"(a[2]), "r"(a[3]), "r"(b[0]), "r"(b[1]));
}

// ---------------- state self projection: Wh_in = fs @ W_in + b_in (fp16 out) ------
__global__ void __launch_bounds__(256, 2) k_gemm_in(const float* __restrict__ fs,
                                                    const float* __restrict__ Win,
                                                    const float* __restrict__ bin) {
    const int M = NS, K = INS;
    int row0 = blockIdx.x * 128;
    int col0 = blockIdx.y * 128;
    __shared__ __half Ah[2][128][24];
    __shared__ __half Bh[2][128][24];
    int tid = threadIdx.x;
    int warp = tid >> 5, lane = tid & 31;
    int wm = warp & 3, wn = warp >> 2;
    int gr = lane >> 2, lc = lane & 3;
    int ar = tid >> 2, ak = (tid & 3) * 4;
    int br = tid >> 5, bc = (tid & 31) * 4;

    float4 la[2], lb[2];
    float c[2][8][4];
    #pragma unroll
    for (int mi = 0; mi < 2; mi++)
        #pragma unroll
        for (int ni = 0; ni < 8; ni++)
            #pragma unroll
            for (int q = 0; q < 4; q++) c[mi][ni][q] = 0.f;

    #pragma unroll
    for (int i = 0; i < 2; i++) {
        la[i] = *(const float4*)(fs + (size_t)(row0 + ar + i * 64) * K + ak);
        lb[i] = *(const float4*)(Win + (size_t)(br + i * 8) * HD + col0 + bc);
    }
    #pragma unroll
    for (int i = 0; i < 2; i++) {
        int r = ar + i * 64;
        Ah[0][r][ak+0]=__float2half_rn(la[i].x); Ah[0][r][ak+1]=__float2half_rn(la[i].y);
        Ah[0][r][ak+2]=__float2half_rn(la[i].z); Ah[0][r][ak+3]=__float2half_rn(la[i].w);
        int kk = br + i * 8;
        Bh[0][bc+0][kk]=__float2half_rn(lb[i].x); Bh[0][bc+1][kk]=__float2half_rn(lb[i].y);
        Bh[0][bc+2][kk]=__float2half_rn(lb[i].z); Bh[0][bc+3][kk]=__float2half_rn(lb[i].w);
    }
    __syncthreads();
    int nk = K / 16;
    for (int kc = 0; kc < nk; kc++) {
        int buf = kc & 1;
        bool nxt = (kc + 1) < nk;
        if (nxt) {
            int kt = (kc + 1) * 16;
            #pragma unroll
            for (int i = 0; i < 2; i++) {
                la[i] = *(const float4*)(fs + (size_t)(row0 + ar + i * 64) * K + kt + ak);
                lb[i] = *(const float4*)(Win + (size_t)(kt + br + i * 8) * HD + col0 + bc);
            }
        }
        {
            unsigned a[2][4], b[8][2];
            #pragma unroll
            for (int mi = 0; mi < 2; mi++) {
                int rb = wm * 32 + mi * 16 + gr;
                a[mi][0] = *(const unsigned*)&Ah[buf][rb][2*lc];
                a[mi][1] = *(const unsigned*)&Ah[buf][rb+8][2*lc];
                a[mi][2] = *(const unsigned*)&Ah[buf][rb][2*lc+8];
                a[mi][3] = *(const unsigned*)&Ah[buf][rb+8][2*lc+8];
            }
            #pragma unroll
            for (int ni = 0; ni < 8; ni++) {
                int cb = wn * 64 + ni * 8 + gr;
                b[ni][0] = *(const unsigned*)&Bh[buf][cb][2*lc];
                b[ni][1] = *(const unsigned*)&Bh[buf][cb][2*lc+8];
            }
            #pragma unroll
            for (int mi = 0; mi < 2; mi++)
                #pragma unroll
                for (int ni = 0; ni < 8; ni++)
                    mma_f16(c[mi][ni], a[mi], b[ni]);
        }
        if (nxt) {
            int nb = buf ^ 1;
            #pragma unroll
            for (int i = 0; i < 2; i++) {
                int r = ar + i * 64;
                Ah[nb][r][ak+0]=__float2half_rn(la[i].x); Ah[nb][r][ak+1]=__float2half_rn(la[i].y);
                Ah[nb][r][ak+2]=__float2half_rn(la[i].z); Ah[nb][r][ak+3]=__float2half_rn(la[i].w);
                int kk = br + i * 8;
                Bh[nb][bc+0][kk]=__float2half_rn(lb[i].x); Bh[nb][bc+1][kk]=__float2half_rn(lb[i].y);
                Bh[nb][bc+2][kk]=__float2half_rn(lb[i].z); Bh[nb][bc+3][kk]=__float2half_rn(lb[i].w);
            }
        }
        __syncthreads();
    }
    #pragma unroll
    for (int mi = 0; mi < 2; mi++) {
        int r0 = row0 + wm * 32 + mi * 16 + gr;
        #pragma unroll
        for (int ni = 0; ni < 8; ni++) {
            int cl = col0 + wn * 64 + ni * 8 + lc * 2;
            float b0 = bin[cl], b1 = bin[cl + 1];
            *(__half2*)(g_Wh_in + (size_t)r0 * HD + cl) =
                __floats2half2_rn(c[mi][ni][0] + b0, c[mi][ni][1] + b1);
            *(__half2*)(g_Wh_in + (size_t)(r0 + 8) * HD + cl) =
                __floats2half2_rn(c[mi][ni][2] + b0, c[mi][ni][3] + b1);
        }
    }
}

// ---------------- CSR build: histogram, scan, scatter ----------------
__global__ void k_hist(const int* __restrict__ ecc_dst, const int* __restrict__ ecs_dst) {
    int gid = blockIdx.x * blockDim.x + threadIdx.x;
    if (gid < 9 * ECC) {
        int r = gid / ECC;
        atomicAdd(&g_cnt_cc[r * NC + ecc_dst[gid]], 1);
    } else if (gid < 9 * ECC + 3 * ECS) {
        int g = gid - 9 * ECC;
        int t = g / ECS;
        atomicAdd(&g_cnt_cs[t * NS + ecs_dst[g]], 1);
    }
}

__global__ void __launch_bounds__(1024) k_scan() {
    int rel = blockIdx.x;
    int n; int* cnt; int* off; int* cur;
    if (rel < 9) { n = NC; cnt = g_cnt_cc + rel * NC; off = g_off_cc + rel * NC; cur = g_cur_cc + rel * NC; }
    else { int t = rel - 9; n = NS; cnt = g_cnt_cs + t * NS; off = g_off_cs + t * NS; cur = g_cur_cs + t * NS; }
    int tid = threadIdx.x;
    int CH = (n + 1023) / 1024;
    int base = tid * CH;
    int loc[10]; int s = 0;
    for (int i = 0; i < CH; i++) {
        int v = (base + i < n) ? cnt[base + i] : 0;
        loc[i] = s; s += v;
    }
    __shared__ int sums[1024];
    sums[tid] = s; __syncthreads();
    for (int o = 1; o < 1024; o <<= 1) {
        int v = (tid >= o) ? sums[tid - o] : 0;
        __syncthreads();
        sums[tid] += v;
        __syncthreads();
    }
    int prefix = (tid == 0) ? 0 : sums[tid - 1];
    for (int i = 0; i < CH; i++) if (base + i < n) {
        int o2 = prefix + loc[i];
        off[base + i] = o2;
        cur[base + i] = o2;
    }
}

__global__ void k_scatter(const int* __restrict__ ecc_src, const int* __restrict__ ecc_dst,
                          const int* __restrict__ ecs_src, const int* __restrict__ ecs_dst) {
    int gid = blockIdx.x * blockDim.x + threadIdx.x;
    if (gid < 9 * ECC) {
        int r = gid / ECC;
        int pos = atomicAdd(&g_cur_cc[r * NC + ecc_dst[gid]], 1);
        g_csr_cc[r * ECC + pos] = ecc_src[gid];
    } else if (gid < 9 * ECC + 3 * ECS) {
        int g = gid - 9 * ECC;
        int t = g / ECS;
        int pos = atomicAdd(&g_cur_cs[t * NS + ecs_dst[g]], 1);
        g_csr_cs[t * ECS + pos] = ecs_src[g];
    }
}

// ---------------- feature-space softmax aggregation ----------------
// AGG_h[dst] = sum_e softmax(a)_e^h * x[src_e]; out later = AGG_h @ W[:,h-block] + b.
__device__ __forceinline__ float lrelu(float x) { return x > 0.f ? x : LALPHA * x; }

__global__ void __launch_bounds__(256) k_gather_agg(const float* __restrict__ f1,
                                                    const float* __restrict__ f2,
                                                    const float* __restrict__ f3) {
    __shared__ float pbuf[8][32][H];
    __shared__ int   sbuf[8][32];
    int y = blockIdx.y;                 // 0..8 cc rel; 9..11 cs rel
    int warp = threadIdx.x >> 5, lane = threadIdx.x & 31;
    bool st = (y >= 9);
    int node = blockIdx.x * 8 + warp;
    if (node >= (st ? NS : NC)) return;

    int beg, cnt;
    const float *asb, *adp, *axp, *feat;
    const int* csr;
    __half* aggp;                       // base of h=0 chunk for this node
    size_t hstride;
    if (!st) {
        int r = y, s = r / 3, d = r % 3;
        beg = g_off_cc[r * NC + node];
        cnt = g_cnt_cc[r * NC + node];
        asb = g_as_cc + (size_t)r * NC * H;
        adp = g_ad_cc + ((size_t)r * NC + node) * H;
        axp = g_asmax + r * H;
        csr = g_csr_cc + (size_t)r * ECC;
        feat = (s == 0) ? f1 : (s == 1) ? f2 : f3;
        aggp = g_agg_c + ((size_t)(d * 8) * NC + node) * KAGG + s * INC;
        hstride = (size_t)NC * KAGG;
    } else {
        int t = y - 9;
        beg = g_off_cs[t * NS + node];
        cnt = g_cnt_cs[t * NS + node];
        asb = g_as_cs + (size_t)t * NC * H;
        adp = g_ad_s + ((size_t)t * NS + node) * H;
        axp = g_asmax + (9 + t) * H;
        csr = g_csr_cs + (size_t)t * ECS;
        feat = (t == 0) ? f1 : (t == 1) ? f2 : f3;
        aggp = g_agg_s + (size_t)node * KAGG + t * INC;
        hstride = (size_t)NS * KAGG;
    }

    float ad[H], M[H];
    {
        float4 a0 = *(const float4*)adp;
        float4 a1 = *(const float4*)(adp + 4);
        float4 x0 = *(const float4*)axp;
        float4 x1 = *(const float4*)(axp + 4);
        ad[0]=a0.x; ad[1]=a0.y; ad[2]=a0.z; ad[3]=a0.w;
        ad[4]=a1.x; ad[5]=a1.y; ad[6]=a1.z; ad[7]=a1.w;
        M[0]=lrelu(x0.x+ad[0]); M[1]=lrelu(x0.y+ad[1]); M[2]=lrelu(x0.z+ad[2]); M[3]=lrelu(x0.w+ad[3]);
        M[4]=lrelu(x1.x+ad[4]); M[5]=lrelu(x1.y+ad[5]); M[6]=lrelu(x1.z+ad[6]); M[7]=lrelu(x1.w+ad[7]);
    }
    float lsum[H];
    #pragma unroll
    for (int h = 0; h < H; h++) lsum[h] = 0.f;
    float acc[H][4];
    #pragma unroll
    for (int h = 0; h < H; h++)
        #pragma unroll
        for (int j = 0; j < 4; j++) acc[h][j] = 0.f;

    int nchunk = (cnt + 31) >> 5;
    for (int c = 0; c < nchunk; c++) {
        int e = c * 32 + lane;
        float p[H];
        int src = 0;
        if (e < cnt) {
            src = __ldg(&csr[beg + e]);
            float4 s0 = *(const float4*)(asb + (size_t)src * H);
            float4 s1 = *(const float4*)(asb + (size_t)src * H + 4);
            float ev[H];
            ev[0]=lrelu(s0.x+ad[0]); ev[1]=lrelu(s0.y+ad[1]); ev[2]=lrelu(s0.z+ad[2]); ev[3]=lrelu(s0.w+ad[3]);
            ev[4]=lrelu(s1.x+ad[4]); ev[5]=lrelu(s1.y+ad[5]); ev[6]=lrelu(s1.z+ad[6]); ev[7]=lrelu(s1.w+ad[7]);
            #pragma unroll
            for (int h = 0; h < H; h++) { p[h] = __expf(ev[h] - M[h]); lsum[h] += p[h]; }
        } else {
            #pragma unroll
            for (int h = 0; h < H; h++) p[h] = 0.f;
        }
        sbuf[warp][lane] = src;
        #pragma unroll
        for (int h = 0; h < H; h++) pbuf[warp][lane][h] = p[h];
        __syncwarp();
        int nv = min(32, cnt - c * 32);
        #pragma unroll 2
        for (int ee = 0; ee < nv; ee++) {
            int s2 = sbuf[warp][ee];
            float4 p0 = *(const float4*)&pbuf[warp][ee][0];   // broadcast
            float4 p1 = *(const float4*)&pbuf[warp][ee][4];
            float4 xv = *(const float4*)(feat + (size_t)s2 * INC + lane * 4);  // coalesced 512B/warp
            float pv[H] = {p0.x, p0.y, p0.z, p0.w, p1.x, p1.y, p1.z, p1.w};
            #pragma unroll
            for (int h = 0; h < H; h++) {
                acc[h][0] += pv[h] * xv.x;
                acc[h][1] += pv[h] * xv.y;
                acc[h][2] += pv[h] * xv.z;
                acc[h][3] += pv[h] * xv.w;
            }
        }
        __syncwarp();
    }
    #pragma unroll
    for (int h = 0; h < H; h++)
        #pragma unroll
        for (int o = 16; o > 0; o >>= 1) lsum[h] += __shfl_xor_sync(0xffffffffu, lsum[h], o);

    #pragma unroll
    for (int h = 0; h < H; h++) {
        float iv = (cnt > 0) ? 1.f / lsum[h] : 0.f;
        __half2 lo = __floats2half2_rn(acc[h][0] * iv, acc[h][1] * iv);
        __half2 hi = __floats2half2_rn(acc[h][2] * iv, acc[h][3] * iv);
        uint2 u;
        u.x = *(unsigned*)&lo; u.y = *(unsigned*)&hi;
        *(uint2*)(aggp + h * hstride + lane * 4) = u;
    }
}

// ---------------- final GEMMs: out = AGG @ W_blk + masked bias (+self) + relu -----
// grid (79, 8, 4): z = dst type (0..2 C, 3 state), y = head. Tile 128 x 32, K=384.
__global__ void __launch_bounds__(256, 2) k_gemm2(const float* __restrict__ Wcc, const float* __restrict__ bcc,
                                                  const float* __restrict__ Wcs, const float* __restrict__ bcs,
                                                  float* __restrict__ out) {
    int z = blockIdx.z, h = blockIdx.y;
    bool st = (z == 3);
    int M = st ? NS : NC;
    int row0 = blockIdx.x * 128;
    if (row0 >= M) return;
    const __half* A = st ? (g_agg_s + (size_t)h * NS * KAGG)
                         : (g_agg_c + (size_t)(z * 8 + h) * NC * KAGG);
    // B row k -> W[(rel(k))][k%128][h*32 + c]
    __shared__ __half Ah[2][128][24];   // 16 k per tile
    __shared__ __half Bh[2][32][24];    // [n][k]

    int tid = threadIdx.x;
    int warp = tid >> 5, lane = tid & 31;
    int gr = lane >> 2, lc = lane & 3;
    int arow = tid >> 1, aoff = (tid & 1) * 8;
    int bcn = tid >> 3, bk2 = (tid & 7) * 2;

    float c[4][4];
    #pragma unroll
    for (int ni = 0; ni < 4; ni++)
        #pragma unroll
        for (int q = 0; q < 4; q++) c[ni][q] = 0.f;

    auto wptr = [&](int k, int col) -> const float* {
        int s = k >> 7, ki = k & 127;
        return st ? (Wcs + ((size_t)s * INC + ki) * HD + h * 32 + col)
                  : (Wcc + ((size_t)(3 * s + z) * INC + ki) * HD + h * 32 + col);
    };

    // prologue
    {
        uint4 av = make_uint4(0,0,0,0);
        if (row0 + arow < M) av = *(const uint4*)(A + (size_t)(row0 + arow) * KAGG + aoff);
        *(uint4*)&Ah[0][arow][aoff] = av;
        float w0 = *wptr(bk2, bcn), w1 = *wptr(bk2 + 1, bcn);
        Bh[0][bcn][bk2]     = __float2half_rn(w0);
        Bh[0][bcn][bk2 + 1] = __float2half_rn(w1);
    }
    __syncthreads();

    const int nk = KAGG / 16;   // 24
    for (int kc = 0; kc < nk; kc++) {
        int buf = kc & 1;
        bool nxt = (kc + 1) < nk;
        uint4 av; float w0, w1;
        if (nxt) {
            int kt = (kc + 1) * 16;
            av = make_uint4(0,0,0,0);
            if (row0 + arow < M) av = *(const uint4*)(A + (size_t)(row0 + arow) * KAGG + kt + aoff);
            w0 = *wptr(kt + bk2, bcn);
            w1 = *wptr(kt + bk2 + 1, bcn);
        }
        {
            unsigned a[4], b[4][2];
            int rb = warp * 16 + gr;
            a[0] = *(const unsigned*)&Ah[buf][rb][2*lc];
            a[1] = *(const unsigned*)&Ah[buf][rb + 8][2*lc];
            a[2] = *(const unsigned*)&Ah[buf][rb][2*lc + 8];
            a[3] = *(const unsigned*)&Ah[buf][rb + 8][2*lc + 8];
            #pragma unroll
            for (int ni = 0; ni < 4; ni++) {
                int cb = ni * 8 + gr;
                b[ni][0] = *(const unsigned*)&Bh[buf][cb][2*lc];
                b[ni][1] = *(const unsigned*)&Bh[buf][cb][2*lc + 8];
            }
            #pragma unroll
            for (int ni = 0; ni < 4; ni++)
                mma_f16(c[ni], a, b[ni]);
        }
        if (nxt) {
            int nb = buf ^ 1;
            *(uint4*)&Ah[nb][arow][aoff] = av;
            Bh[nb][bcn][bk2]     = __float2half_rn(w0);
            Bh[nb][bcn][bk2 + 1] = __float2half_rn(w1);
        }
        __syncthreads();
    }

    // epilogue: masked bias (+ state self), relu, write out
    #pragma unroll
    for (int half = 0; half < 2; half++) {
        int r = row0 + warp * 16 + gr + half * 8;
        if (r >= M) continue;
        // per-row relation mask
        bool m0, m1, m2;
        if (st) {
            m0 = g_cnt_cs[0 * NS + r] > 0;
            m1 = g_cnt_cs[1 * NS + r] > 0;
            m2 = g_cnt_cs[2 * NS + r] > 0;
        } else {
            m0 = g_cnt_cc[(0 + z) * NC + r] > 0;
            m1 = g_cnt_cc[(3 + z) * NC + r] > 0;
            m2 = g_cnt_cc[(6 + z) * NC + r] > 0;
        }
        #pragma unroll
        for (int ni = 0; ni < 4; ni++) {
            int cl = h * 32 + ni * 8 + lc * 2;
            float b0 = 0.f, b1 = 0.f;
            if (st) {
                if (m0) { b0 += bcs[0 * HD + cl]; b1 += bcs[0 * HD + cl + 1]; }
                if (m1) { b0 += bcs[1 * HD + cl]; b1 += bcs[1 * HD + cl + 1]; }
                if (m2) { b0 += bcs[2 * HD + cl]; b1 += bcs[2 * HD + cl + 1]; }
                __half2 sv = *(const __half2*)(g_Wh_in + (size_t)r * HD + cl);
                float2 sf = __half22float2(sv);
                b0 += sf.x; b1 += sf.y;
            } else {
                if (m0) { b0 += bcc[(size_t)(0 + z) * HD + cl]; b1 += bcc[(size_t)(0 + z) * HD + cl + 1]; }
                if (m1) { b0 += bcc[(size_t)(3 + z) * HD + cl]; b1 += bcc[(size_t)(3 + z) * HD + cl + 1]; }
                if (m2) { b0 += bcc[(size_t)(6 + z) * HD + cl]; b1 += bcc[(size_t)(6 + z) * HD + cl + 1]; }
            }
            float v0 = c[ni][half * 2 + 0] + b0;
            float v1 = c[ni][half * 2 + 1] + b1;
            float* o = st ? (out + (size_t)3 * NC * HD + (size_t)r * HD + cl)
                          : (out + ((size_t)z * NC + r) * HD + cl);
            *(float2*)o = make_float2(fmaxf(v0, 0.f), fmaxf(v1, 0.f));
        }
    }
}

// ---------------- launch: fork/join two independent chains ----------------
static cudaStream_t g_s1 = 0;
static cudaEvent_t g_evFork = 0, g_evCsr = 0;

extern "C" void kernel_launch(void* const* d_in, const int* in_sizes, int n_in,
                              void* d_out, int out_size) {
    const float* f1      = (const float*)d_in[0];
    const float* f2      = (const float*)d_in[1];
    const float* f3      = (const float*)d_in[2];
    const float* fs      = (const float*)d_in[3];
    const float* W_node  = (const float*)d_in[4];
    const float* b_node  = (const float*)d_in[5];
    const float* W_cc    = (const float*)d_in[6];
    const float* b_cc    = (const float*)d_in[7];
    const float* W_cs    = (const float*)d_in[8];
    const float* b_cs    = (const float*)d_in[9];
    const float* W_in    = (const float*)d_in[10];
    const float* b_in    = (const float*)d_in[11];
    const float* attn_cc = (const float*)d_in[12];
    const float* attn_cs = (const float*)d_in[13];
    const int* ecc_src   = (const int*)d_in[14];
    const int* ecc_dst   = (const int*)d_in[15];
    const int* ecs_src   = (const int*)d_in[16];
    const int* ecs_dst   = (const int*)d_in[17];
    float* out = (float*)d_out;

    if (!g_s1) {
        cudaStreamCreateWithFlags(&g_s1, cudaStreamNonBlocking);
        cudaEventCreateWithFlags(&g_evFork, cudaEventDisableTiming);
        cudaEventCreateWithFlags(&g_evCsr, cudaEventDisableTiming);
    }

    int tot = 9 * ECC + 3 * ECS;

    // fork: CSR chain on s1 (depends only on edge lists)
    cudaEventRecord(g_evFork, 0);
    cudaStreamWaitEvent(g_s1, g_evFork, 0);
    k_zero_counters<<<(9 * NC + 255) / 256, 256, 0, g_s1>>>();
    k_hist<<<(tot + 255) / 256, 256, 0, g_s1>>>(ecc_dst, ecs_dst);
    k_scan<<<12, 1024, 0, g_s1>>>();
    k_scatter<<<(tot + 255) / 256, 256, 0, g_s1>>>(ecc_src, ecc_dst, ecs_src, ecs_dst);
    cudaEventRecord(g_evCsr, g_s1);

    // main stream: attention-scalar chain + state self projection
    k_wred<<<(24 * INC * H + 255) / 256, 256>>>(W_node, b_node, W_cc, b_cc, W_cs, b_cs, W_in, b_in, attn_cc, attn_cs);
    k_skinny<<<dim3(1250, 4), 256>>>(f1, f2, f3, fs);
    k_asmax<<<12, 256>>>();
    k_gemm_in<<<dim3(8, 2), 256>>>(fs, W_in, b_in);

    // join CSR, then feature-space aggregation, then final GEMMs
    cudaStreamWaitEvent(0, g_evCsr, 0);
    k_gather_agg<<<dim3(1250, 12), 256>>>(f1, f2, f3);
    k_gemm2<<<dim3(79, 8, 4), 256>>>(W_cc, b_cc, W_cs, b_cs, out);
}

// round 13
// speedup vs baseline: 1.6628x; 1.6628x over previous
#include <cuda_runtime.h>
#include <cuda_fp16.h>
#include <cstdint>

#define H   8
#define Dd  32
#define HD  256
#define NC  10000
#define NS  1024
#define INC 128
#define INS 64
#define ECC 120000
#define ECS 10000
#define LALPHA 0.2f
#define NEG_BIG -1e30f

// ---------------- device scratch (static; no runtime allocation) ----------------
__device__ float g_Wh_cc[9u * NC * HD];     // 92 MB fp32 (issue-bound gather: no cvt)
__device__ float g_Wh_cs[3u * NC * HD];
__device__ float g_Wh_in[NS * HD];

__device__ float g_as_cc[9 * NC * H];
__device__ float g_ad_cc[9 * NC * H];
__device__ float g_as_cs[3 * NC * H];
__device__ float g_ad_s[3 * NS * H];

__device__ float g_asmax[12 * H];            // per-(relation, head) max of a_src

__device__ float g_wred_as[9 * INC * H];
__device__ float g_wred_ad[9 * INC * H];
__device__ float g_wred_as_cs[3 * INC * H];
__device__ float g_wred_ad_s[3 * INS * H];
__device__ float g_bred_as[9 * H];
__device__ float g_bred_ad[9 * H];
__device__ float g_bred_as_cs[3 * H];
__device__ float g_bred_ad_s[3 * H];

__device__ int g_cnt_cc[9 * NC];
__device__ int g_off_cc[9 * NC];
__device__ int g_cur_cc[9 * NC];
__device__ int g_csr_cc[9 * ECC];
__device__ int g_cnt_cs[3 * NS];
__device__ int g_off_cs[3 * NS];
__device__ int g_cur_cs[3 * NS];
__device__ int g_csr_cs[3 * ECS];

// ---------------- zero counters ----------------
__global__ void k_zero_counters() {
    int i = blockIdx.x * blockDim.x + threadIdx.x;
    if (i < 9 * NC) g_cnt_cc[i] = 0;
    if (i < 3 * NS) g_cnt_cs[i] = 0;
}

// ---------------- reduce attention vectors into weights ----------------
__global__ void k_wred(const float* __restrict__ W_node, const float* __restrict__ b_node,
                       const float* __restrict__ W_cc,   const float* __restrict__ b_cc,
                       const float* __restrict__ W_cs,   const float* __restrict__ b_cs,
                       const float* __restrict__ W_in,   const float* __restrict__ b_in,
                       const float* __restrict__ attn_cc, const float* __restrict__ attn_cs) {
    int gid = blockIdx.x * blockDim.x + threadIdx.x;
    if (gid >= 24 * INC * H) return;
    int j   = gid / (INC * H);
    int rem = gid % (INC * H);
    int k = rem / H, h = rem % H;
    const float *Wsrc, *att, *bvec;
    float *dst, *bdst;
    int Kin = INC;
    if (j < 9) {
        Wsrc = W_cc + (size_t)j * INC * HD;
        att  = attn_cc + (size_t)(j * 2 + 0) * HD;
        bvec = b_cc + (size_t)j * HD;
        dst  = g_wred_as + j * INC * H; bdst = g_bred_as + j * H;
    } else if (j < 18) {
        int r = j - 9;
        Wsrc = W_node + (size_t)(r % 3) * INC * HD;
        att  = attn_cc + (size_t)(r * 2 + 1) * HD;
        bvec = b_node + (size_t)(r % 3) * HD;
        dst  = g_wred_ad + r * INC * H; bdst = g_bred_ad + r * H;
    } else if (j < 21) {
        int t = j - 18;
        Wsrc = W_cs + (size_t)t * INC * HD;
        att  = attn_cs + (size_t)(t * 2 + 0) * HD;
        bvec = b_cs + (size_t)t * HD;
        dst  = g_wred_as_cs + t * INC * H; bdst = g_bred_as_cs + t * H;
    } else {
        int t = j - 21;
        Wsrc = W_in;
        att  = attn_cs + (size_t)(t * 2 + 1) * HD;
        bvec = b_in;
        dst  = g_wred_ad_s + t * INS * H; bdst = g_bred_ad_s + t * H;
        Kin = INS;
    }
    if (k >= Kin) return;
    float s = 0.f;
    #pragma unroll
    for (int d = 0; d < Dd; d++)
        s += Wsrc[(size_t)k * HD + h * Dd + d] * att[h * Dd + d];
    dst[k * H + h] = s;
    if (k == 0) {
        float bs = 0.f;
        #pragma unroll
        for (int d = 0; d < Dd; d++) bs += bvec[h * Dd + d] * att[h * Dd + d];
        bdst[h] = bs;
    }
}

// ---------------- fused skinny GEMMs: one pass over each node type ----------
__global__ void __launch_bounds__(256) k_skinny(const float* __restrict__ f1,
                                                const float* __restrict__ f2,
                                                const float* __restrict__ f3,
                                                const float* __restrict__ fs) {
    int t = blockIdx.y;
    __shared__ float Ws[7][H][INC];
    __shared__ float bsm[7][H];
    __shared__ const float* wptr[7];
    __shared__ float* optr[7];
    __shared__ const float* bptr[7];

    int Kin = (t < 3) ? INC : INS;
    int nG  = (t < 3) ? 7 : 3;
    int nNodes = (t < 3) ? NC : NS;
    const float* feat = (t == 0) ? f1 : (t == 1) ? f2 : (t == 2) ? f3 : fs;

    if (threadIdx.x < (unsigned)nG) {
        int g = threadIdx.x;
        if (t < 3) {
            if (g < 3) {
                int r = t * 3 + g;
                wptr[g] = g_wred_as + r * INC * H;
                bptr[g] = g_bred_as + r * H;
                optr[g] = g_as_cc + (size_t)r * NC * H;
            } else if (g < 6) {
                int r = (g - 3) * 3 + t;
                wptr[g] = g_wred_ad + r * INC * H;
                bptr[g] = g_bred_ad + r * H;
                optr[g] = g_ad_cc + (size_t)r * NC * H;
            } else {
                wptr[g] = g_wred_as_cs + t * INC * H;
                bptr[g] = g_bred_as_cs + t * H;
                optr[g] = g_as_cs + (size_t)t * NC * H;
            }
        } else {
            wptr[g] = g_wred_ad_s + g * INS * H;
            bptr[g] = g_bred_ad_s + g * H;
            optr[g] = g_ad_s + (size_t)g * NS * H;
        }
    }
    __syncthreads();

    for (int idx = threadIdx.x; idx < nG * H * Kin; idx += 256) {
        int g = idx / (H * Kin);
        int rem = idx % (H * Kin);
        int h = rem / Kin, k = rem % Kin;
        Ws[g][h][k] = wptr[g][k * H + h];
    }
    if (threadIdx.x < (unsigned)(nG * H)) {
        int g = threadIdx.x / H, h = threadIdx.x % H;
        bsm[g][h] = bptr[g][h];
    }
    __syncthreads();

    int warp = threadIdx.x >> 5, lane = threadIdx.x & 31;
    int node = blockIdx.x * 8 + warp;
    if (node >= nNodes) return;
    const float* frow = feat + (size_t)node * Kin;
    float f[4];
    int nc = Kin / 32;
    for (int c = 0; c < nc; c++) f[c] = frow[c * 32 + lane];

    for (int g = 0; g < nG; g++) {
        float mine = 0.f;
        #pragma unroll
        for (int h = 0; h < H; h++) {
            float v = 0.f;
            for (int c = 0; c < nc; c++) v += f[c] * Ws[g][h][c * 32 + lane];
            #pragma unroll
            for (int o = 16; o > 0; o >>= 1) v += __shfl_xor_sync(0xffffffffu, v, o);
            if (lane == h) mine = v;
        }
        if (lane < H) optr[g][(size_t)node * H + lane] = mine + bsm[g][lane];
    }
}

// ---------------- per-relation a_src max (for single-pass softmax) ----------
__global__ void __launch_bounds__(256) k_asmax() {
    int rel = blockIdx.x;
    const float* asb = (rel < 9) ? (g_as_cc + (size_t)rel * NC * H)
                                 : (g_as_cs + (size_t)(rel - 9) * NC * H);
    float mx[H];
    #pragma unroll
    for (int h = 0; h < H; h++) mx[h] = NEG_BIG;
    for (int i = threadIdx.x; i < NC; i += 256) {
        float4 a0 = *(const float4*)(asb + (size_t)i * H);
        float4 a1 = *(const float4*)(asb + (size_t)i * H + 4);
        mx[0]=fmaxf(mx[0],a0.x); mx[1]=fmaxf(mx[1],a0.y); mx[2]=fmaxf(mx[2],a0.z); mx[3]=fmaxf(mx[3],a0.w);
        mx[4]=fmaxf(mx[4],a1.x); mx[5]=fmaxf(mx[5],a1.y); mx[6]=fmaxf(mx[6],a1.z); mx[7]=fmaxf(mx[7],a1.w);
    }
    #pragma unroll
    for (int h = 0; h < H; h++)
        #pragma unroll
        for (int o = 16; o > 0; o >>= 1) mx[h] = fmaxf(mx[h], __shfl_xor_sync(0xffffffffu, mx[h], o));
    __shared__ float sm[8][H];
    int warp = threadIdx.x >> 5, lane = threadIdx.x & 31;
    if (lane == 0)
        #pragma unroll
        for (int h = 0; h < H; h++) sm[warp][h] = mx[h];
    __syncthreads();
    if (threadIdx.x < H) {
        float v = sm[0][threadIdx.x];
        #pragma unroll
        for (int w = 1; w < 8; w++) v = fmaxf(v, sm[w][threadIdx.x]);
        g_asmax[rel * H + threadIdx.x] = v;
    }
}

// ---------------- FP16 HMMA helper ----------------
__device__ __forceinline__ void mma_f16(float c[4], const unsigned a[4], const unsigned b[2]) {
    asm volatile("mma.sync.aligned.m16n8k16.row.col.f32.f16.f16.f32 "
        "{%0,%1,%2,%3}, {%4,%5,%6,%7}, {%8,%9}, {%0,%1,%2,%3};"
        : "+f"(c[0]), "+f"(c[1]), "+f"(c[2]), "+f"(c[3])
        : "r"(a[0]), "r"(a[1]), "r"(a[2]), "r"(a[3]), "r"(b[0]), "r"(b[1]));
}

// ---------------- big GEMMs: 13 jobs, FP16 HMMA m16n8k16, fp32 output ----------
__global__ void __launch_bounds__(256, 2) k_gemm(const float* __restrict__ f1, const float* __restrict__ f2,
                                                 const float* __restrict__ f3, const float* __restrict__ fs,
                                                 const float* __restrict__ Wcc, const float* __restrict__ bcc,
                                                 const float* __restrict__ Wcs, const float* __restrict__ bcs,
                                                 const float* __restrict__ Win, const float* __restrict__ bin) {
    int z = blockIdx.z;
    const float* A; const float* W; const float* bptr; float* outp; int M, K;
    if (z < 9) {
        int s = z / 3;
        A = (s == 0) ? f1 : (s == 1) ? f2 : f3;
        W = Wcc + (size_t)z * INC * HD; bptr = bcc + (size_t)z * HD;
        outp = g_Wh_cc + (size_t)z * NC * HD; M = NC; K = INC;
    } else if (z < 12) {
        int t = z - 9;
        A = (t == 0) ? f1 : (t == 1) ? f2 : f3;
        W = Wcs + (size_t)t * INC * HD; bptr = bcs + (size_t)t * HD;
        outp = g_Wh_cs + (size_t)t * NC * HD; M = NC; K = INC;
    } else {
        A = fs; W = Win; bptr = bin; outp = g_Wh_in; M = NS; K = INS;
    }
    int row0 = blockIdx.x * 128;
    if (row0 >= M) return;
    int col0 = blockIdx.y * 128;

    __shared__ __half Ah[2][128][24];
    __shared__ __half Bh[2][128][24];

    int tid = threadIdx.x;
    int warp = tid >> 5, lane = tid & 31;
    int wm = warp & 3, wn = warp >> 2;
    int gr = lane >> 2, lc = lane & 3;

    int ar = tid >> 2, ak = (tid & 3) * 4;
    int br = tid >> 5, bc = (tid & 31) * 4;

    float4 la[2], lb[2];
    float c[2][8][4];
    #pragma unroll
    for (int mi = 0; mi < 2; mi++)
        #pragma unroll
        for (int ni = 0; ni < 8; ni++)
            #pragma unroll
            for (int q = 0; q < 4; q++) c[mi][ni][q] = 0.f;

    #pragma unroll
    for (int i = 0; i < 2; i++) {
        int r = ar + i * 64;
        la[i] = make_float4(0.f, 0.f, 0.f, 0.f);
        if (row0 + r < M) la[i] = *(const float4*)(A + (size_t)(row0 + r) * K + ak);
        lb[i] = *(const float4*)(W + (size_t)(br + i * 8) * HD + col0 + bc);
    }
    #pragma unroll
    for (int i = 0; i < 2; i++) {
        int r = ar + i * 64;
        Ah[0][r][ak + 0] = __float2half_rn(la[i].x); Ah[0][r][ak + 1] = __float2half_rn(la[i].y);
        Ah[0][r][ak + 2] = __float2half_rn(la[i].z); Ah[0][r][ak + 3] = __float2half_rn(la[i].w);
        int kk = br + i * 8;
        Bh[0][bc + 0][kk] = __float2half_rn(lb[i].x);
        Bh[0][bc + 1][kk] = __float2half_rn(lb[i].y);
        Bh[0][bc + 2][kk] = __float2half_rn(lb[i].z);
        Bh[0][bc + 3][kk] = __float2half_rn(lb[i].w);
    }
    __syncthreads();

    int nk = K / 16;
    for (int kc = 0; kc < nk; kc++) {
        int buf = kc & 1;
        bool nxt = (kc + 1) < nk;
        if (nxt) {
            int kt = (kc + 1) * 16;
            #pragma unroll
            for (int i = 0; i < 2; i++) {
                int r = ar + i * 64;
                la[i] = make_float4(0.f, 0.f, 0.f, 0.f);
                if (row0 + r < M) la[i] = *(const float4*)(A + (size_t)(row0 + r) * K + kt + ak);
                lb[i] = *(const float4*)(W + (size_t)(kt + br + i * 8) * HD + col0 + bc);
            }
        }
        {
            unsigned a[2][4], b[8][2];
            #pragma unroll
            for (int mi = 0; mi < 2; mi++) {
                int rb = wm * 32 + mi * 16 + gr;
                a[mi][0] = *(const unsigned*)&Ah[buf][rb][2 * lc];
                a[mi][1] = *(const unsigned*)&Ah[buf][rb + 8][2 * lc];
                a[mi][2] = *(const unsigned*)&Ah[buf][rb][2 * lc + 8];
                a[mi][3] = *(const unsigned*)&Ah[buf][rb + 8][2 * lc + 8];
            }
            #pragma unroll
            for (int ni = 0; ni < 8; ni++) {
                int cb = wn * 64 + ni * 8 + gr;
                b[ni][0] = *(const unsigned*)&Bh[buf][cb][2 * lc];
                b[ni][1] = *(const unsigned*)&Bh[buf][cb][2 * lc + 8];
            }
            #pragma unroll
            for (int mi = 0; mi < 2; mi++)
                #pragma unroll
                for (int ni = 0; ni < 8; ni++)
                    mma_f16(c[mi][ni], a[mi], b[ni]);
        }
        if (nxt) {
            int nb = buf ^ 1;
            #pragma unroll
            for (int i = 0; i < 2; i++) {
                int r = ar + i * 64;
                Ah[nb][r][ak + 0] = __float2half_rn(la[i].x); Ah[nb][r][ak + 1] = __float2half_rn(la[i].y);
                Ah[nb][r][ak + 2] = __float2half_rn(la[i].z); Ah[nb][r][ak + 3] = __float2half_rn(la[i].w);
                int kk = br + i * 8;
                Bh[nb][bc + 0][kk] = __float2half_rn(lb[i].x);
                Bh[nb][bc + 1][kk] = __float2half_rn(lb[i].y);
                Bh[nb][bc + 2][kk] = __float2half_rn(lb[i].z);
                Bh[nb][bc + 3][kk] = __float2half_rn(lb[i].w);
            }
        }
        __syncthreads();
    }

    #pragma unroll
    for (int mi = 0; mi < 2; mi++) {
        int r0 = row0 + wm * 32 + mi * 16 + gr;
        #pragma unroll
        for (int ni = 0; ni < 8; ni++) {
            int cl = col0 + wn * 64 + ni * 8 + lc * 2;
            float b0 = bptr[cl], b1 = bptr[cl + 1];
            if (r0 < M)
                *(float2*)(outp + (size_t)r0 * HD + cl) =
                    make_float2(c[mi][ni][0] + b0, c[mi][ni][1] + b1);
            if (r0 + 8 < M)
                *(float2*)(outp + (size_t)(r0 + 8) * HD + cl) =
                    make_float2(c[mi][ni][2] + b0, c[mi][ni][3] + b1);
        }
    }
}

// ---------------- CSR build: histogram, scan, scatter ----------------
__global__ void k_hist(const int* __restrict__ ecc_dst, const int* __restrict__ ecs_dst) {
    int gid = blockIdx.x * blockDim.x + threadIdx.x;
    if (gid < 9 * ECC) {
        int r = gid / ECC;
        atomicAdd(&g_cnt_cc[r * NC + ecc_dst[gid]], 1);
    } else if (gid < 9 * ECC + 3 * ECS) {
        int g = gid - 9 * ECC;
        int t = g / ECS;
        atomicAdd(&g_cnt_cs[t * NS + ecs_dst[g]], 1);
    }
}

__global__ void __launch_bounds__(1024) k_scan() {
    int rel = blockIdx.x;
    int n; int* cnt; int* off; int* cur;
    if (rel < 9) { n = NC; cnt = g_cnt_cc + rel * NC; off = g_off_cc + rel * NC; cur = g_cur_cc + rel * NC; }
    else { int t = rel - 9; n = NS; cnt = g_cnt_cs + t * NS; off = g_off_cs + t * NS; cur = g_cur_cs + t * NS; }
    int tid = threadIdx.x;
    int CH = (n + 1023) / 1024;
    int base = tid * CH;
    int loc[10]; int s = 0;
    for (int i = 0; i < CH; i++) {
        int v = (base + i < n) ? cnt[base + i] : 0;
        loc[i] = s; s += v;
    }
    __shared__ int sums[1024];
    sums[tid] = s; __syncthreads();
    for (int o = 1; o < 1024; o <<= 1) {
        int v = (tid >= o) ? sums[tid - o] : 0;
        __syncthreads();
        sums[tid] += v;
        __syncthreads();
    }
    int prefix = (tid == 0) ? 0 : sums[tid - 1];
    for (int i = 0; i < CH; i++) if (base + i < n) {
        int o2 = prefix + loc[i];
        off[base + i] = o2;
        cur[base + i] = o2;
    }
}

__global__ void k_scatter(const int* __restrict__ ecc_src, const int* __restrict__ ecc_dst,
                          const int* __restrict__ ecs_src, const int* __restrict__ ecs_dst) {
    int gid = blockIdx.x * blockDim.x + threadIdx.x;
    if (gid < 9 * ECC) {
        int r = gid / ECC;
        int pos = atomicAdd(&g_cur_cc[r * NC + ecc_dst[gid]], 1);
        g_csr_cc[r * ECC + pos] = ecc_src[gid];
    } else if (gid < 9 * ECC + 3 * ECS) {
        int g = gid - 9 * ECC;
        int t = g / ECS;
        int pos = atomicAdd(&g_cur_cs[t * NS + ecs_dst[g]], 1);
        g_csr_cs[t * ECS + pos] = ecs_src[g];
    }
}

// ---------------- fused single-pass softmax + gather ----------------
__device__ __forceinline__ float lrelu(float x) { return x > 0.f ? x : LALPHA * x; }

__device__ __forceinline__ float sel8(const float v[8], int hq) {
    float a = (hq & 1) ? v[1] : v[0];
    float b = (hq & 1) ? v[3] : v[2];
    float c = (hq & 1) ? v[5] : v[4];
    float d = (hq & 1) ? v[7] : v[6];
    float ab = (hq & 2) ? b : a;
    float cd = (hq & 2) ? d : c;
    return (hq & 4) ? cd : ab;
}

// Single pass, upper-bound max, smem-staged coalesced consume.
// fp32 Wh: per edge = 2 LDS + 2 LDG.128 + 16 FFMA, zero cvt (minimum instr count).
__device__ __forceinline__ void gat_relation(
    int lane, int warp, int hq, int beg, int cnt,
    const float* __restrict__ asb, const float* __restrict__ adp,
    const float* __restrict__ axp,
    const int* __restrict__ csr, const float* __restrict__ Wh,
    float pbuf[8][32][H], int sbuf[8][32], float outacc[8])
{
    float ad[H], M[H];
    {
        float4 a0 = *(const float4*)adp;
        float4 a1 = *(const float4*)(adp + 4);
        float4 x0 = *(const float4*)axp;
        float4 x1 = *(const float4*)(axp + 4);
        ad[0]=a0.x; ad[1]=a0.y; ad[2]=a0.z; ad[3]=a0.w;
        ad[4]=a1.x; ad[5]=a1.y; ad[6]=a1.z; ad[7]=a1.w;
        M[0]=lrelu(x0.x+ad[0]); M[1]=lrelu(x0.y+ad[1]); M[2]=lrelu(x0.z+ad[2]); M[3]=lrelu(x0.w+ad[3]);
        M[4]=lrelu(x1.x+ad[4]); M[5]=lrelu(x1.y+ad[5]); M[6]=lrelu(x1.z+ad[6]); M[7]=lrelu(x1.w+ad[7]);
    }
    float lsum[H];
    #pragma unroll
    for (int h = 0; h < H; h++) lsum[h] = 0.f;
    float acc[8] = {};
    int nchunk = (cnt + 31) >> 5;
    for (int c = 0; c < nchunk; c++) {
        int e = c * 32 + lane;
        float p[H];
        int src = 0;
        if (e < cnt) {
            src = __ldg(&csr[beg + e]);
            float4 s0 = *(const float4*)(asb + (size_t)src * H);
            float4 s1 = *(const float4*)(asb + (size_t)src * H + 4);
            float ev[H];
            ev[0]=lrelu(s0.x+ad[0]); ev[1]=lrelu(s0.y+ad[1]); ev[2]=lrelu(s0.z+ad[2]); ev[3]=lrelu(s0.w+ad[3]);
            ev[4]=lrelu(s1.x+ad[4]); ev[5]=lrelu(s1.y+ad[5]); ev[6]=lrelu(s1.z+ad[6]); ev[7]=lrelu(s1.w+ad[7]);
            #pragma unroll
            for (int h = 0; h < H; h++) { p[h] = __expf(ev[h] - M[h]); lsum[h] += p[h]; }
        } else {
            #pragma unroll
            for (int h = 0; h < H; h++) p[h] = 0.f;
        }
        sbuf[warp][lane] = src;
        #pragma unroll
        for (int h = 0; h < H; h++) pbuf[warp][lane][h] = p[h];
        __syncwarp();
        int nv = min(32, cnt - c * 32);
        #pragma unroll 4
        for (int ee = 0; ee < nv; ee++) {
            int s2 = sbuf[warp][ee];
            float cf = pbuf[warp][ee][hq];
            const float* wr = Wh + (size_t)s2 * HD + lane * 8;
            float4 w0 = *(const float4*)wr;
            float4 w1 = *(const float4*)(wr + 4);
            acc[0] += cf * w0.x; acc[1] += cf * w0.y; acc[2] += cf * w0.z; acc[3] += cf * w0.w;
            acc[4] += cf * w1.x; acc[5] += cf * w1.y; acc[6] += cf * w1.z; acc[7] += cf * w1.w;
        }
        __syncwarp();
    }
    #pragma unroll
    for (int h = 0; h < H; h++)
        #pragma unroll
        for (int o = 16; o > 0; o >>= 1) lsum[h] += __shfl_xor_sync(0xffffffffu, lsum[h], o);
    float invs = 1.f / sel8(lsum, hq);
    #pragma unroll
    for (int j = 0; j < 8; j++) outacc[j] += acc[j] * invs;
}

__global__ void __launch_bounds__(256) k_gather_cc(float* __restrict__ out) {
    __shared__ float pbuf[8][32][H];
    __shared__ int   sbuf[8][32];
    int dt = blockIdx.y;
    int warp = threadIdx.x >> 5, lane = threadIdx.x & 31;
    int node = blockIdx.x * 8 + warp;
    if (node >= NC) return;
    int hq = lane >> 2;

    float outacc[8] = {};
    #pragma unroll 1
    for (int s = 0; s < 3; s++) {
        int r = 3 * s + dt;
        int beg = g_off_cc[r * NC + node];
        int cnt = g_cnt_cc[r * NC + node];
        if (cnt == 0) continue;
        gat_relation(lane, warp, hq, beg, cnt,
                     g_as_cc + (size_t)r * NC * H,
                     g_ad_cc + ((size_t)r * NC + node) * H,
                     g_asmax + r * H,
                     g_csr_cc + (size_t)r * ECC,
                     g_Wh_cc + (size_t)r * NC * HD,
                     pbuf, sbuf, outacc);
    }
    float* o = out + ((size_t)dt * NC + node) * HD + lane * 8;
    float4 v0, v1;
    v0.x = fmaxf(outacc[0], 0.f); v0.y = fmaxf(outacc[1], 0.f);
    v0.z = fmaxf(outacc[2], 0.f); v0.w = fmaxf(outacc[3], 0.f);
    v1.x = fmaxf(outacc[4], 0.f); v1.y = fmaxf(outacc[5], 0.f);
    v1.z = fmaxf(outacc[6], 0.f); v1.w = fmaxf(outacc[7], 0.f);
    *(float4*)o = v0; *(float4*)(o + 4) = v1;
}

__global__ void __launch_bounds__(256) k_gather_state(float* __restrict__ out) {
    __shared__ float pbuf[8][32][H];
    __shared__ int   sbuf[8][32];
    int warp = threadIdx.x >> 5, lane = threadIdx.x & 31;
    int node = blockIdx.x * 8 + warp;
    if (node >= NS) return;
    int hq = lane >> 2;

    float outacc[8];
    {   // self term
        const float* sp = g_Wh_in + (size_t)node * HD + lane * 8;
        float4 s0 = *(const float4*)sp;
        float4 s1 = *(const float4*)(sp + 4);
        outacc[0]=s0.x; outacc[1]=s0.y; outacc[2]=s0.z; outacc[3]=s0.w;
        outacc[4]=s1.x; outacc[5]=s1.y; outacc[6]=s1.z; outacc[7]=s1.w;
    }

    #pragma unroll 1
    for (int t = 0; t < 3; t++) {
        int beg = g_off_cs[t * NS + node];
        int cnt = g_cnt_cs[t * NS + node];
        if (cnt == 0) continue;
        gat_relation(lane, warp, hq, beg, cnt,
                     g_as_cs + (size_t)t * NC * H,
                     g_ad_s + ((size_t)t * NS + node) * H,
                     g_asmax + (9 + t) * H,
                     g_csr_cs + (size_t)t * ECS,
                     g_Wh_cs + (size_t)t * NC * HD,
                     pbuf, sbuf, outacc);
    }
    float* o = out + (size_t)3 * NC * HD + (size_t)node * HD + lane * 8;
    float4 v0, v1;
    v0.x = fmaxf(outacc[0], 0.f); v0.y = fmaxf(outacc[1], 0.f);
    v0.z = fmaxf(outacc[2], 0.f); v0.w = fmaxf(outacc[3], 0.f);
    v1.x = fmaxf(outacc[4], 0.f); v1.y = fmaxf(outacc[5], 0.f);
    v1.z = fmaxf(outacc[6], 0.f); v1.w = fmaxf(outacc[7], 0.f);
    *(float4*)o = v0; *(float4*)(o + 4) = v1;
}

// ---------------- launch: fork/join two independent chains ----------------
static cudaStream_t g_s1 = 0;
static cudaEvent_t g_evFork = 0, g_evCsr = 0, g_evComp = 0, g_evState = 0;

extern "C" void kernel_launch(void* const* d_in, const int* in_sizes, int n_in,
                              void* d_out, int out_size) {
    const float* f1      = (const float*)d_in[0];
    const float* f2      = (const float*)d_in[1];
    const float* f3      = (const float*)d_in[2];
    const float* fs      = (const float*)d_in[3];
    const float* W_node  = (const float*)d_in[4];
    const float* b_node  = (const float*)d_in[5];
    const float* W_cc    = (const float*)d_in[6];
    const float* b_cc    = (const float*)d_in[7];
    const float* W_cs    = (const float*)d_in[8];
    const float* b_cs    = (const float*)d_in[9];
    const float* W_in    = (const float*)d_in[10];
    const float* b_in    = (const float*)d_in[11];
    const float* attn_cc = (const float*)d_in[12];
    const float* attn_cs = (const float*)d_in[13];
    const int* ecc_src   = (const int*)d_in[14];
    const int* ecc_dst   = (const int*)d_in[15];
    const int* ecs_src   = (const int*)d_in[16];
    const int* ecs_dst   = (const int*)d_in[17];
    float* out = (float*)d_out;

    if (!g_s1) {   // lazy init on first (uncaptured) call; no device memory allocated
        cudaStreamCreateWithFlags(&g_s1, cudaStreamNonBlocking);
        cudaEventCreateWithFlags(&g_evFork, cudaEventDisableTiming);
        cudaEventCreateWithFlags(&g_evCsr, cudaEventDisableTiming);
        cudaEventCreateWithFlags(&g_evComp, cudaEventDisableTiming);
        cudaEventCreateWithFlags(&g_evState, cudaEventDisableTiming);
    }

    int tot = 9 * ECC + 3 * ECS;

    // fork: CSR chain on s1 (depends only on edge lists)
    cudaEventRecord(g_evFork, 0);
    cudaStreamWaitEvent(g_s1, g_evFork, 0);
    k_zero_counters<<<(9 * NC + 255) / 256, 256, 0, g_s1>>>();
    k_hist<<<(tot + 255) / 256, 256, 0, g_s1>>>(ecc_dst, ecs_dst);
    k_scan<<<12, 1024, 0, g_s1>>>();
    k_scatter<<<(tot + 255) / 256, 256, 0, g_s1>>>(ecc_src, ecc_dst, ecs_src, ecs_dst);
    cudaEventRecord(g_evCsr, g_s1);

    // main stream: projection chain
    k_wred<<<(24 * INC * H + 255) / 256, 256>>>(W_node, b_node, W_cc, b_cc, W_cs, b_cs, W_in, b_in, attn_cc, attn_cs);
    k_skinny<<<dim3(1250, 4), 256>>>(f1, f2, f3, fs);
    k_asmax<<<12, 256>>>();
    k_gemm<<<dim3(79, 2, 13), 256>>>(f1, f2, f3, fs, W_cc, b_cc, W_cs, b_cs, W_in, b_in);
    cudaEventRecord(g_evComp, 0);

    // state gather on s1 (after CSR chain, stream-ordered; + compute)
    cudaStreamWaitEvent(g_s1, g_evComp, 0);
    k_gather_state<<<128, 256, 0, g_s1>>>(out);
    cudaEventRecord(g_evState, g_s1);

    // cc gather on main stream (after compute, stream-ordered; + CSR)
    cudaStreamWaitEvent(0, g_evCsr, 0);
    k_gather_cc<<<dim3(1250, 3), 256>>>(out);

    // join state branch back
    cudaStreamWaitEvent(0, g_evState, 0);
}

// round 15
// speedup vs baseline: 1.7165x; 1.0323x over previous
#include <cuda_runtime.h>
#include <cuda_fp16.h>
#include <cstdint>

#define H   8
#define Dd  32
#define HD  256
#define NC  10000
#define NS  1024
#define INC 128
#define INS 64
#define ECC 120000
#define ECS 10000
#define LALPHA 0.2f
#define NEG_BIG -1e30f

// ---------------- device scratch (static; no runtime allocation) ----------------
__device__ __half g_Wh_cc[9u * NC * HD];     // 46 MB (fp16)
__device__ __half g_Wh_cs[3u * NC * HD];     // 15 MB
__device__ __half g_Wh_in[NS * HD];

__device__ float g_as_cc[9 * NC * H];
__device__ float g_ad_cc[9 * NC * H];
__device__ float g_as_cs[3 * NC * H];
__device__ float g_ad_s[3 * NS * H];

__device__ float g_asmax[12 * H];            // per-(relation, head) max of a_src

__device__ float g_wred_as[9 * INC * H];
__device__ float g_wred_ad[9 * INC * H];
__device__ float g_wred_as_cs[3 * INC * H];
__device__ float g_wred_ad_s[3 * INS * H];
__device__ float g_bred_as[9 * H];
__device__ float g_bred_ad[9 * H];
__device__ float g_bred_as_cs[3 * H];
__device__ float g_bred_ad_s[3 * H];

__device__ int g_cnt_cc[9 * NC];
__device__ int g_off_cc[9 * NC];
__device__ int g_cur_cc[9 * NC];
__device__ int g_csr_cc[9 * ECC];
__device__ int g_cnt_cs[3 * NS];
__device__ int g_off_cs[3 * NS];
__device__ int g_cur_cs[3 * NS];
__device__ int g_csr_cs[3 * ECS];

// ---------------- zero counters ----------------
__global__ void k_zero_counters() {
    int i = blockIdx.x * blockDim.x + threadIdx.x;
    if (i < 9 * NC) g_cnt_cc[i] = 0;
    if (i < 3 * NS) g_cnt_cs[i] = 0;
}

// ---------------- reduce attention vectors into weights ----------------
__global__ void k_wred(const float* __restrict__ W_node, const float* __restrict__ b_node,
                       const float* __restrict__ W_cc,   const float* __restrict__ b_cc,
                       const float* __restrict__ W_cs,   const float* __restrict__ b_cs,
                       const float* __restrict__ W_in,   const float* __restrict__ b_in,
                       const float* __restrict__ attn_cc, const float* __restrict__ attn_cs) {
    int gid = blockIdx.x * blockDim.x + threadIdx.x;
    if (gid >= 24 * INC * H) return;
    int j   = gid / (INC * H);
    int rem = gid % (INC * H);
    int k = rem / H, h = rem % H;
    const float *Wsrc, *att, *bvec;
    float *dst, *bdst;
    int Kin = INC;
    if (j < 9) {
        Wsrc = W_cc + (size_t)j * INC * HD;
        att  = attn_cc + (size_t)(j * 2 + 0) * HD;
        bvec = b_cc + (size_t)j * HD;
        dst  = g_wred_as + j * INC * H; bdst = g_bred_as + j * H;
    } else if (j < 18) {
        int r = j - 9;
        Wsrc = W_node + (size_t)(r % 3) * INC * HD;
        att  = attn_cc + (size_t)(r * 2 + 1) * HD;
        bvec = b_node + (size_t)(r % 3) * HD;
        dst  = g_wred_ad + r * INC * H; bdst = g_bred_ad + r * H;
    } else if (j < 21) {
        int t = j - 18;
        Wsrc = W_cs + (size_t)t * INC * HD;
        att  = attn_cs + (size_t)(t * 2 + 0) * HD;
        bvec = b_cs + (size_t)t * HD;
        dst  = g_wred_as_cs + t * INC * H; bdst = g_bred_as_cs + t * H;
    } else {
        int t = j - 21;
        Wsrc = W_in;
        att  = attn_cs + (size_t)(t * 2 + 1) * HD;
        bvec = b_in;
        dst  = g_wred_ad_s + t * INS * H; bdst = g_bred_ad_s + t * H;
        Kin = INS;
    }
    if (k >= Kin) return;
    float s = 0.f;
    #pragma unroll
    for (int d = 0; d < Dd; d++)
        s += Wsrc[(size_t)k * HD + h * Dd + d] * att[h * Dd + d];
    dst[k * H + h] = s;
    if (k == 0) {
        float bs = 0.f;
        #pragma unroll
        for (int d = 0; d < Dd; d++) bs += bvec[h * Dd + d] * att[h * Dd + d];
        bdst[h] = bs;
    }
}

// ---------------- fused skinny GEMMs: one pass over each node type ----------
__global__ void __launch_bounds__(256) k_skinny(const float* __restrict__ f1,
                                                const float* __restrict__ f2,
                                                const float* __restrict__ f3,
                                                const float* __restrict__ fs) {
    int t = blockIdx.y;
    __shared__ float Ws[7][H][INC];
    __shared__ float bsm[7][H];
    __shared__ const float* wptr[7];
    __shared__ float* optr[7];
    __shared__ const float* bptr[7];

    int Kin = (t < 3) ? INC : INS;
    int nG  = (t < 3) ? 7 : 3;
    int nNodes = (t < 3) ? NC : NS;
    const float* feat = (t == 0) ? f1 : (t == 1) ? f2 : (t == 2) ? f3 : fs;

    if (threadIdx.x < (unsigned)nG) {
        int g = threadIdx.x;
        if (t < 3) {
            if (g < 3) {
                int r = t * 3 + g;
                wptr[g] = g_wred_as + r * INC * H;
                bptr[g] = g_bred_as + r * H;
                optr[g] = g_as_cc + (size_t)r * NC * H;
            } else if (g < 6) {
                int r = (g - 3) * 3 + t;
                wptr[g] = g_wred_ad + r * INC * H;
                bptr[g] = g_bred_ad + r * H;
                optr[g] = g_ad_cc + (size_t)r * NC * H;
            } else {
                wptr[g] = g_wred_as_cs + t * INC * H;
                bptr[g] = g_bred_as_cs + t * H;
                optr[g] = g_as_cs + (size_t)t * NC * H;
            }
        } else {
            wptr[g] = g_wred_ad_s + g * INS * H;
            bptr[g] = g_bred_ad_s + g * H;
            optr[g] = g_ad_s + (size_t)g * NS * H;
        }
    }
    __syncthreads();

    for (int idx = threadIdx.x; idx < nG * H * Kin; idx += 256) {
        int g = idx / (H * Kin);
        int rem = idx % (H * Kin);
        int h = rem / Kin, k = rem % Kin;
        Ws[g][h][k] = wptr[g][k * H + h];
    }
    if (threadIdx.x < (unsigned)(nG * H)) {
        int g = threadIdx.x / H, h = threadIdx.x % H;
        bsm[g][h] = bptr[g][h];
    }
    __syncthreads();

    int warp = threadIdx.x >> 5, lane = threadIdx.x & 31;
    int node = blockIdx.x * 8 + warp;
    if (node >= nNodes) return;
    const float* frow = feat + (size_t)node * Kin;
    float f[4];
    int nc = Kin / 32;
    for (int c = 0; c < nc; c++) f[c] = frow[c * 32 + lane];

    for (int g = 0; g < nG; g++) {
        float mine = 0.f;
        #pragma unroll
        for (int h = 0; h < H; h++) {
            float v = 0.f;
            for (int c = 0; c < nc; c++) v += f[c] * Ws[g][h][c * 32 + lane];
            #pragma unroll
            for (int o = 16; o > 0; o >>= 1) v += __shfl_xor_sync(0xffffffffu, v, o);
            if (lane == h) mine = v;
        }
        if (lane < H) optr[g][(size_t)node * H + lane] = mine + bsm[g][lane];
    }
}

// ---------------- per-relation a_src max (for single-pass softmax) ----------
__global__ void __launch_bounds__(256) k_asmax() {
    int rel = blockIdx.x;
    const float* asb = (rel < 9) ? (g_as_cc + (size_t)rel * NC * H)
                                 : (g_as_cs + (size_t)(rel - 9) * NC * H);
    float mx[H];
    #pragma unroll
    for (int h = 0; h < H; h++) mx[h] = NEG_BIG;
    for (int i = threadIdx.x; i < NC; i += 256) {
        float4 a0 = *(const float4*)(asb + (size_t)i * H);
        float4 a1 = *(const float4*)(asb + (size_t)i * H + 4);
        mx[0]=fmaxf(mx[0],a0.x); mx[1]=fmaxf(mx[1],a0.y); mx[2]=fmaxf(mx[2],a0.z); mx[3]=fmaxf(mx[3],a0.w);
        mx[4]=fmaxf(mx[4],a1.x); mx[5]=fmaxf(mx[5],a1.y); mx[6]=fmaxf(mx[6],a1.z); mx[7]=fmaxf(mx[7],a1.w);
    }
    #pragma unroll
    for (int h = 0; h < H; h++)
        #pragma unroll
        for (int o = 16; o > 0; o >>= 1) mx[h] = fmaxf(mx[h], __shfl_xor_sync(0xffffffffu, mx[h], o));
    __shared__ float sm[8][H];
    int warp = threadIdx.x >> 5, lane = threadIdx.x & 31;
    if (lane == 0)
        #pragma unroll
        for (int h = 0; h < H; h++) sm[warp][h] = mx[h];
    __syncthreads();
    if (threadIdx.x < H) {
        float v = sm[0][threadIdx.x];
        #pragma unroll
        for (int w = 1; w < 8; w++) v = fmaxf(v, sm[w][threadIdx.x]);
        g_asmax[rel * H + threadIdx.x] = v;
    }
}

// ---------------- FP16 HMMA helper ----------------
__device__ __forceinline__ void mma_f16(float c[4], const unsigned a[4], const unsigned b[2]) {
    asm volatile("mma.sync.aligned.m16n8k16.row.col.f32.f16.f16.f32 "
        "{%0,%1,%2,%3}, {%4,%5,%6,%7}, {%8,%9}, {%0,%1,%2,%3};"
        : "+f"(c[0]), "+f"(c[1]), "+f"(c[2]), "+f"(c[3])
        : "r"(a[0]), "r"(a[1]), "r"(a[2]), "r"(a[3]), "r"(b[0]), "r"(b[1]));
}

// ---------------- big GEMMs: grouped launches for GEMM<->gather pipelining ------
// group 0..2: jobs {g, 3+g, 6+g} (cc relations feeding gather dst-type g)
// group 3   : jobs {9, 10, 11, 12} (cs relations + state self, feeding gather_state)
__global__ void __launch_bounds__(256, 2) k_gemm(int group,
                                                 const float* __restrict__ f1, const float* __restrict__ f2,
                                                 const float* __restrict__ f3, const float* __restrict__ fs,
                                                 const float* __restrict__ Wcc, const float* __restrict__ bcc,
                                                 const float* __restrict__ Wcs, const float* __restrict__ bcs,
                                                 const float* __restrict__ Win, const float* __restrict__ bin) {
    int z = (group < 3) ? (group + 3 * (int)blockIdx.z) : (9 + (int)blockIdx.z);
    const float* A; const float* W; const float* bptr; __half* outp; int M, K;
    if (z < 9) {
        int s = z / 3;
        A = (s == 0) ? f1 : (s == 1) ? f2 : f3;
        W = Wcc + (size_t)z * INC * HD; bptr = bcc + (size_t)z * HD;
        outp = g_Wh_cc + (size_t)z * NC * HD; M = NC; K = INC;
    } else if (z < 12) {
        int t = z - 9;
        A = (t == 0) ? f1 : (t == 1) ? f2 : f3;
        W = Wcs + (size_t)t * INC * HD; bptr = bcs + (size_t)t * HD;
        outp = g_Wh_cs + (size_t)t * NC * HD; M = NC; K = INC;
    } else {
        A = fs; W = Win; bptr = bin; outp = g_Wh_in; M = NS; K = INS;
    }
    int row0 = blockIdx.x * 128;
    if (row0 >= M) return;
    int col0 = blockIdx.y * 128;

    __shared__ __half Ah[2][128][24];
    __shared__ __half Bh[2][128][24];

    int tid = threadIdx.x;
    int warp = tid >> 5, lane = tid & 31;
    int wm = warp & 3, wn = warp >> 2;
    int gr = lane >> 2, lc = lane & 3;

    int ar = tid >> 2, ak = (tid & 3) * 4;
    int br = tid >> 5, bc = (tid & 31) * 4;

    float4 la[2], lb[2];
    float c[2][8][4];
    #pragma unroll
    for (int mi = 0; mi < 2; mi++)
        #pragma unroll
        for (int ni = 0; ni < 8; ni++)
            #pragma unroll
            for (int q = 0; q < 4; q++) c[mi][ni][q] = 0.f;

    #pragma unroll
    for (int i = 0; i < 2; i++) {
        int r = ar + i * 64;
        la[i] = make_float4(0.f, 0.f, 0.f, 0.f);
        if (row0 + r < M) la[i] = *(const float4*)(A + (size_t)(row0 + r) * K + ak);
        lb[i] = *(const float4*)(W + (size_t)(br + i * 8) * HD + col0 + bc);
    }
    #pragma unroll
    for (int i = 0; i < 2; i++) {
        int r = ar + i * 64;
        Ah[0][r][ak + 0] = __float2half_rn(la[i].x); Ah[0][r][ak + 1] = __float2half_rn(la[i].y);
        Ah[0][r][ak + 2] = __float2half_rn(la[i].z); Ah[0][r][ak + 3] = __float2half_rn(la[i].w);
        int kk = br + i * 8;
        Bh[0][bc + 0][kk] = __float2half_rn(lb[i].x);
        Bh[0][bc + 1][kk] = __float2half_rn(lb[i].y);
        Bh[0][bc + 2][kk] = __float2half_rn(lb[i].z);
        Bh[0][bc + 3][kk] = __float2half_rn(lb[i].w);
    }
    __syncthreads();

    int nk = K / 16;
    for (int kc = 0; kc < nk; kc++) {
        int buf = kc & 1;
        bool nxt = (kc + 1) < nk;
        if (nxt) {
            int kt = (kc + 1) * 16;
            #pragma unroll
            for (int i = 0; i < 2; i++) {
                int r = ar + i * 64;
                la[i] = make_float4(0.f, 0.f, 0.f, 0.f);
                if (row0 + r < M) la[i] = *(const float4*)(A + (size_t)(row0 + r) * K + kt + ak);
                lb[i] = *(const float4*)(W + (size_t)(kt + br + i * 8) * HD + col0 + bc);
            }
        }
        {
            unsigned a[2][4], b[8][2];
            #pragma unroll
            for (int mi = 0; mi < 2; mi++) {
                int rb = wm * 32 + mi * 16 + gr;
                a[mi][0] = *(const unsigned*)&Ah[buf][rb][2 * lc];
                a[mi][1] = *(const unsigned*)&Ah[buf][rb + 8][2 * lc];
                a[mi][2] = *(const unsigned*)&Ah[buf][rb][2 * lc + 8];
                a[mi][3] = *(const unsigned*)&Ah[buf][rb + 8][2 * lc + 8];
            }
            #pragma unroll
            for (int ni = 0; ni < 8; ni++) {
                int cb = wn * 64 + ni * 8 + gr;
                b[ni][0] = *(const unsigned*)&Bh[buf][cb][2 * lc];
                b[ni][1] = *(const unsigned*)&Bh[buf][cb][2 * lc + 8];
            }
            #pragma unroll
            for (int mi = 0; mi < 2; mi++)
                #pragma unroll
                for (int ni = 0; ni < 8; ni++)
                    mma_f16(c[mi][ni], a[mi], b[ni]);
        }
        if (nxt) {
            int nb = buf ^ 1;
            #pragma unroll
            for (int i = 0; i < 2; i++) {
                int r = ar + i * 64;
                Ah[nb][r][ak + 0] = __float2half_rn(la[i].x); Ah[nb][r][ak + 1] = __float2half_rn(la[i].y);
                Ah[nb][r][ak + 2] = __float2half_rn(la[i].z); Ah[nb][r][ak + 3] = __float2half_rn(la[i].w);
                int kk = br + i * 8;
                Bh[nb][bc + 0][kk] = __float2half_rn(lb[i].x);
                Bh[nb][bc + 1][kk] = __float2half_rn(lb[i].y);
                Bh[nb][bc + 2][kk] = __float2half_rn(lb[i].z);
                Bh[nb][bc + 3][kk] = __float2half_rn(lb[i].w);
            }
        }
        __syncthreads();
    }

    #pragma unroll
    for (int mi = 0; mi < 2; mi++) {
        int r0 = row0 + wm * 32 + mi * 16 + gr;
        #pragma unroll
        for (int ni = 0; ni < 8; ni++) {
            int cl = col0 + wn * 64 + ni * 8 + lc * 2;
            float b0 = bptr[cl], b1 = bptr[cl + 1];
            if (r0 < M)
                *(__half2*)(outp + (size_t)r0 * HD + cl) =
                    __floats2half2_rn(c[mi][ni][0] + b0, c[mi][ni][1] + b1);
            if (r0 + 8 < M)
                *(__half2*)(outp + (size_t)(r0 + 8) * HD + cl) =
                    __floats2half2_rn(c[mi][ni][2] + b0, c[mi][ni][3] + b1);
        }
    }
}

// ---------------- CSR build: histogram, scan, scatter ----------------
__global__ void k_hist(const int* __restrict__ ecc_dst, const int* __restrict__ ecs_dst) {
    int gid = blockIdx.x * blockDim.x + threadIdx.x;
    if (gid < 9 * ECC) {
        int r = gid / ECC;
        atomicAdd(&g_cnt_cc[r * NC + ecc_dst[gid]], 1);
    } else if (gid < 9 * ECC + 3 * ECS) {
        int g = gid - 9 * ECC;
        int t = g / ECS;
        atomicAdd(&g_cnt_cs[t * NS + ecs_dst[g]], 1);
    }
}

__global__ void __launch_bounds__(1024) k_scan() {
    int rel = blockIdx.x;
    int n; int* cnt; int* off; int* cur;
    if (rel < 9) { n = NC; cnt = g_cnt_cc + rel * NC; off = g_off_cc + rel * NC; cur = g_cur_cc + rel * NC; }
    else { int t = rel - 9; n = NS; cnt = g_cnt_cs + t * NS; off = g_off_cs + t * NS; cur = g_cur_cs + t * NS; }
    int tid = threadIdx.x;
    int CH = (n + 1023) / 1024;
    int base = tid * CH;
    int loc[10]; int s = 0;
    for (int i = 0; i < CH; i++) {
        int v = (base + i < n) ? cnt[base + i] : 0;
        loc[i] = s; s += v;
    }
    __shared__ int sums[1024];
    sums[tid] = s; __syncthreads();
    for (int o = 1; o < 1024; o <<= 1) {
        int v = (tid >= o) ? sums[tid - o] : 0;
        __syncthreads();
        sums[tid] += v;
        __syncthreads();
    }
    int prefix = (tid == 0) ? 0 : sums[tid - 1];
    for (int i = 0; i < CH; i++) if (base + i < n) {
        int o2 = prefix + loc[i];
        off[base + i] = o2;
        cur[base + i] = o2;
    }
}

__global__ void k_scatter(const int* __restrict__ ecc_src, const int* __restrict__ ecc_dst,
                          const int* __restrict__ ecs_src, const int* __restrict__ ecs_dst) {
    int gid = blockIdx.x * blockDim.x + threadIdx.x;
    if (gid < 9 * ECC) {
        int r = gid / ECC;
        int pos = atomicAdd(&g_cur_cc[r * NC + ecc_dst[gid]], 1);
        g_csr_cc[r * ECC + pos] = ecc_src[gid];
    } else if (gid < 9 * ECC + 3 * ECS) {
        int g = gid - 9 * ECC;
        int t = g / ECS;
        int pos = atomicAdd(&g_cur_cs[t * NS + ecs_dst[g]], 1);
        g_csr_cs[t * ECS + pos] = ecs_src[g];
    }
}

// ---------------- fused single-pass softmax + gather ----------------
__device__ __forceinline__ float lrelu(float x) { return x > 0.f ? x : LALPHA * x; }

__device__ __forceinline__ float sel8(const float v[8], int hq) {
    float a = (hq & 1) ? v[1] : v[0];
    float b = (hq & 1) ? v[3] : v[2];
    float c = (hq & 1) ? v[5] : v[4];
    float d = (hq & 1) ? v[7] : v[6];
    float ab = (hq & 2) ? b : a;
    float cd = (hq & 2) ? d : c;
    return (hq & 4) ? cd : ab;
}

__device__ __forceinline__ void gat_relation(
    int lane, int warp, int hq, int beg, int cnt,
    const float* __restrict__ asb, const float* __restrict__ adp,
    const float* __restrict__ axp,
    const int* __restrict__ csr, const __half* __restrict__ Wh,
    float pbuf[8][32][H], int sbuf[8][32], float outacc[8])
{
    float ad[H], M[H];
    {
        float4 a0 = *(const float4*)adp;
        float4 a1 = *(const float4*)(adp + 4);
        float4 x0 = *(const float4*)axp;
        float4 x1 = *(const float4*)(axp + 4);
        ad[0]=a0.x; ad[1]=a0.y; ad[2]=a0.z; ad[3]=a0.w;
        ad[4]=a1.x; ad[5]=a1.y; ad[6]=a1.z; ad[7]=a1.w;
        M[0]=lrelu(x0.x+ad[0]); M[1]=lrelu(x0.y+ad[1]); M[2]=lrelu(x0.z+ad[2]); M[3]=lrelu(x0.w+ad[3]);
        M[4]=lrelu(x1.x+ad[4]); M[5]=lrelu(x1.y+ad[5]); M[6]=lrelu(x1.z+ad[6]); M[7]=lrelu(x1.w+ad[7]);
    }
    float lsum[H];
    #pragma unroll
    for (int h = 0; h < H; h++) lsum[h] = 0.f;
    float acc[8] = {};
    int nchunk = (cnt + 31) >> 5;
    for (int c = 0; c < nchunk; c++) {
        int e = c * 32 + lane;
        float p[H];
        int src = 0;
        if (e < cnt) {
            src = __ldg(&csr[beg + e]);
            float4 s0 = *(const float4*)(asb + (size_t)src * H);
            float4 s1 = *(const float4*)(asb + (size_t)src * H + 4);
            float ev[H];
            ev[0]=lrelu(s0.x+ad[0]); ev[1]=lrelu(s0.y+ad[1]); ev[2]=lrelu(s0.z+ad[2]); ev[3]=lrelu(s0.w+ad[3]);
            ev[4]=lrelu(s1.x+ad[4]); ev[5]=lrelu(s1.y+ad[5]); ev[6]=lrelu(s1.z+ad[6]); ev[7]=lrelu(s1.w+ad[7]);
            #pragma unroll
            for (int h = 0; h < H; h++) { p[h] = __expf(ev[h] - M[h]); lsum[h] += p[h]; }
        } else {
            #pragma unroll
            for (int h = 0; h < H; h++) p[h] = 0.f;
        }
        sbuf[warp][lane] = src;
        #pragma unroll
        for (int h = 0; h < H; h++) pbuf[warp][lane][h] = p[h];
        __syncwarp();
        int nv = min(32, cnt - c * 32);
        #pragma unroll 4
        for (int ee = 0; ee < nv; ee++) {
            int s2 = sbuf[warp][ee];
            float cf = pbuf[warp][ee][hq];
            uint4 u = *(const uint4*)(Wh + (size_t)s2 * HD + lane * 8);
            __half2 h0 = *(__half2*)&u.x, h1 = *(__half2*)&u.y;
            __half2 h2 = *(__half2*)&u.z, h3 = *(__half2*)&u.w;
            float2 f0 = __half22float2(h0), f1 = __half22float2(h1);
            float2 f2 = __half22float2(h2), f3 = __half22float2(h3);
            acc[0] += cf * f0.x; acc[1] += cf * f0.y;
            acc[2] += cf * f1.x; acc[3] += cf * f1.y;
            acc[4] += cf * f2.x; acc[5] += cf * f2.y;
            acc[6] += cf * f3.x; acc[7] += cf * f3.y;
        }
        __syncwarp();
    }
    #pragma unroll
    for (int h = 0; h < H; h++)
        #pragma unroll
        for (int o = 16; o > 0; o >>= 1) lsum[h] += __shfl_xor_sync(0xffffffffu, lsum[h], o);
    float invs = 1.f / sel8(lsum, hq);
    #pragma unroll
    for (int j = 0; j < 8; j++) outacc[j] += acc[j] * invs;
}

// gather for one C dst-type (dt passed as param so each can launch as soon as
// its 3 Wh relation blocks are ready)
__global__ void __launch_bounds__(256) k_gather_cc(int dt, float* __restrict__ out) {
    __shared__ float pbuf[8][32][H];
    __shared__ int   sbuf[8][32];
    int warp = threadIdx.x >> 5, lane = threadIdx.x & 31;
    int node = blockIdx.x * 8 + warp;
    if (node >= NC) return;
    int hq = lane >> 2;

    float outacc[8] = {};
    #pragma unroll 1
    for (int s = 0; s < 3; s++) {
        int r = 3 * s + dt;
        int beg = g_off_cc[r * NC + node];
        int cnt = g_cnt_cc[r * NC + node];
        if (cnt == 0) continue;
        gat_relation(lane, warp, hq, beg, cnt,
                     g_as_cc + (size_t)r * NC * H,
                     g_ad_cc + ((size_t)r * NC + node) * H,
                     g_asmax + r * H,
                     g_csr_cc + (size_t)r * ECC,
                     g_Wh_cc + (size_t)r * NC * HD,
                     pbuf, sbuf, outacc);
    }
    float* o = out + ((size_t)dt * NC + node) * HD + lane * 8;
    float4 v0, v1;
    v0.x = fmaxf(outacc[0], 0.f); v0.y = fmaxf(outacc[1], 0.f);
    v0.z = fmaxf(outacc[2], 0.f); v0.w = fmaxf(outacc[3], 0.f);
    v1.x = fmaxf(outacc[4], 0.f); v1.y = fmaxf(outacc[5], 0.f);
    v1.z = fmaxf(outacc[6], 0.f); v1.w = fmaxf(outacc[7], 0.f);
    *(float4*)o = v0; *(float4*)(o + 4) = v1;
}

__global__ void __launch_bounds__(256) k_gather_state(float* __restrict__ out) {
    __shared__ float pbuf[8][32][H];
    __shared__ int   sbuf[8][32];
    int warp = threadIdx.x >> 5, lane = threadIdx.x & 31;
    int node = blockIdx.x * 8 + warp;
    if (node >= NS) return;
    int hq = lane >> 2;

    float outacc[8] = {};
    {   // self term
        uint4 u = *(const uint4*)(g_Wh_in + (size_t)node * HD + lane * 8);
        __half2 h0 = *(__half2*)&u.x, h1 = *(__half2*)&u.y;
        __half2 h2 = *(__half2*)&u.z, h3 = *(__half2*)&u.w;
        float2 f0 = __half22float2(h0), f1 = __half22float2(h1);
        float2 f2 = __half22float2(h2), f3 = __half22float2(h3);
        outacc[0]=f0.x; outacc[1]=f0.y; outacc[2]=f1.x; outacc[3]=f1.y;
        outacc[4]=f2.x; outacc[5]=f2.y; outacc[6]=f3.x; outacc[7]=f3.y;
    }

    #pragma unroll 1
    for (int t = 0; t < 3; t++) {
        int beg = g_off_cs[t * NS + node];
        int cnt = g_cnt_cs[t * NS + node];
        if (cnt == 0) continue;
        gat_relation(lane, warp, hq, beg, cnt,
                     g_as_cs + (size_t)t * NC * H,
                     g_ad_s + ((size_t)t * NS + node) * H,
                     g_asmax + (9 + t) * H,
                     g_csr_cs + (size_t)t * ECS,
                     g_Wh_cs + (size_t)t * NC * HD,
                     pbuf, sbuf, outacc);
    }
    float* o = out + (size_t)3 * NC * HD + (size_t)node * HD + lane * 8;
    float4 v0, v1;
    v0.x = fmaxf(outacc[0], 0.f); v0.y = fmaxf(outacc[1], 0.f);
    v0.z = fmaxf(outacc[2], 0.f); v0.w = fmaxf(outacc[3], 0.f);
    v1.x = fmaxf(outacc[4], 0.f); v1.y = fmaxf(outacc[5], 0.f);
    v1.z = fmaxf(outacc[6], 0.f); v1.w = fmaxf(outacc[7], 0.f);
    *(float4*)o = v0; *(float4*)(o + 4) = v1;
}

// ---------------- launch: pipelined GEMM groups <-> gather slices ----------------
static cudaStream_t g_s1 = 0;
static cudaEvent_t g_evFork = 0, g_evG[4] = {0,0,0,0}, g_evDone = 0;

extern "C" void kernel_launch(void* const* d_in, const int* in_sizes, int n_in,
                              void* d_out, int out_size) {
    const float* f1      = (const float*)d_in[0];
    const float* f2      = (const float*)d_in[1];
    const float* f3      = (const float*)d_in[2];
    const float* fs      = (const float*)d_in[3];
    const float* W_node  = (const float*)d_in[4];
    const float* b_node  = (const float*)d_in[5];
    const float* W_cc    = (const float*)d_in[6];
    const float* b_cc    = (const float*)d_in[7];
    const float* W_cs    = (const float*)d_in[8];
    const float* b_cs    = (const float*)d_in[9];
    const float* W_in    = (const float*)d_in[10];
    const float* b_in    = (const float*)d_in[11];
    const float* attn_cc = (const float*)d_in[12];
    const float* attn_cs = (const float*)d_in[13];
    const int* ecc_src   = (const int*)d_in[14];
    const int* ecc_dst   = (const int*)d_in[15];
    const int* ecs_src   = (const int*)d_in[16];
    const int* ecs_dst   = (const int*)d_in[17];
    float* out = (float*)d_out;

    if (!g_s1) {   // lazy init on first (uncaptured) call; no device memory allocated
        cudaStreamCreateWithFlags(&g_s1, cudaStreamNonBlocking);
        cudaEventCreateWithFlags(&g_evFork, cudaEventDisableTiming);
        for (int i = 0; i < 4; i++)
            cudaEventCreateWithFlags(&g_evG[i], cudaEventDisableTiming);
        cudaEventCreateWithFlags(&g_evDone, cudaEventDisableTiming);
    }

    int tot = 9 * ECC + 3 * ECS;

    // fork: CSR chain on s1 (depends only on edge lists)
    cudaEventRecord(g_evFork, 0);
    cudaStreamWaitEvent(g_s1, g_evFork, 0);
    k_zero_counters<<<(9 * NC + 255) / 256, 256, 0, g_s1>>>();
    k_hist<<<(tot + 255) / 256, 256, 0, g_s1>>>(ecc_dst, ecs_dst);
    k_scan<<<12, 1024, 0, g_s1>>>();
    k_scatter<<<(tot + 255) / 256, 256, 0, g_s1>>>(ecc_src, ecc_dst, ecs_src, ecs_dst);
    // (CSR ready on s1 in stream order for the gathers below)

    // main stream: projection chain; GEMM split into 4 groups, event after each
    k_wred<<<(24 * INC * H + 255) / 256, 256>>>(W_node, b_node, W_cc, b_cc, W_cs, b_cs, W_in, b_in, attn_cc, attn_cs);
    k_skinny<<<dim3(1250, 4), 256>>>(f1, f2, f3, fs);
    k_asmax<<<12, 256>>>();
    for (int g = 0; g < 4; g++) {
        int nz = (g < 3) ? 3 : 4;
        k_gemm<<<dim3(79, 2, nz), 256>>>(g, f1, f2, f3, fs, W_cc, b_cc, W_cs, b_cs, W_in, b_in);
        cudaEventRecord(g_evG[g], 0);
    }

    // s1: gathers, each starting as soon as its GEMM group (and CSR) is ready;
    // remaining GEMM groups execute concurrently on the main stream.
    for (int g = 0; g < 3; g++) {
        cudaStreamWaitEvent(g_s1, g_evG[g], 0);
        k_gather_cc<<<1250, 256, 0, g_s1>>>(g, out);
    }
    cudaStreamWaitEvent(g_s1, g_evG[3], 0);
    k_gather_state<<<128, 256, 0, g_s1>>>(out);
    cudaEventRecord(g_evDone, g_s1);

    // join back to main stream
    cudaStreamWaitEvent(0, g_evDone, 0);
}

// round 16
// speedup vs baseline: 1.8701x; 1.0895x over previous
#include <cuda_runtime.h>
#include <cuda_fp16.h>
#include <cstdint>

#define H   8
#define Dd  32
#define HD  256
#define NC  10000
#define NS  1024
#define INC 128
#define INS 64
#define ECC 120000
#define ECS 10000
#define LALPHA 0.2f
#define NEG_BIG -1e30f

// ---------------- device scratch (static; no runtime allocation) ----------------
__device__ __half g_Wh_cc[9u * NC * HD];     // 46 MB (fp16)
__device__ __half g_Wh_cs[3u * NC * HD];     // 15 MB
__device__ __half g_Wh_in[NS * HD];

__device__ float g_as_cc[9 * NC * H];
__device__ float g_ad_cc[9 * NC * H];
__device__ float g_as_cs[3 * NC * H];
__device__ float g_ad_s[3 * NS * H];

__device__ float g_asmax[12 * H];            // per-(relation, head) max of a_src

__device__ float g_wred_as[9 * INC * H];
__device__ float g_wred_ad[9 * INC * H];
__device__ float g_wred_as_cs[3 * INC * H];
__device__ float g_wred_ad_s[3 * INS * H];
__device__ float g_bred_as[9 * H];
__device__ float g_bred_ad[9 * H];
__device__ float g_bred_as_cs[3 * H];
__device__ float g_bred_ad_s[3 * H];

__device__ int g_cnt_cc[9 * NC];
__device__ int g_off_cc[9 * NC];
__device__ int g_cur_cc[9 * NC];
__device__ int g_csr_cc[9 * ECC];
__device__ int g_cnt_cs[3 * NS];
__device__ int g_off_cs[3 * NS];
__device__ int g_cur_cs[3 * NS];
__device__ int g_csr_cs[3 * ECS];

// ---------------- zero counters ----------------
__global__ void k_zero_counters() {
    int i = blockIdx.x * blockDim.x + threadIdx.x;
    if (i < 9 * NC) g_cnt_cc[i] = 0;
    if (i < 3 * NS) g_cnt_cs[i] = 0;
}

// ---------------- reduce attention vectors into weights ----------------
__global__ void k_wred(const float* __restrict__ W_node, const float* __restrict__ b_node,
                       const float* __restrict__ W_cc,   const float* __restrict__ b_cc,
                       const float* __restrict__ W_cs,   const float* __restrict__ b_cs,
                       const float* __restrict__ W_in,   const float* __restrict__ b_in,
                       const float* __restrict__ attn_cc, const float* __restrict__ attn_cs) {
    int gid = blockIdx.x * blockDim.x + threadIdx.x;
    if (gid >= 24 * INC * H) return;
    int j   = gid / (INC * H);
    int rem = gid % (INC * H);
    int k = rem / H, h = rem % H;
    const float *Wsrc, *att, *bvec;
    float *dst, *bdst;
    int Kin = INC;
    if (j < 9) {
        Wsrc = W_cc + (size_t)j * INC * HD;
        att  = attn_cc + (size_t)(j * 2 + 0) * HD;
        bvec = b_cc + (size_t)j * HD;
        dst  = g_wred_as + j * INC * H; bdst = g_bred_as + j * H;
    } else if (j < 18) {
        int r = j - 9;
        Wsrc = W_node + (size_t)(r % 3) * INC * HD;
        att  = attn_cc + (size_t)(r * 2 + 1) * HD;
        bvec = b_node + (size_t)(r % 3) * HD;
        dst  = g_wred_ad + r * INC * H; bdst = g_bred_ad + r * H;
    } else if (j < 21) {
        int t = j - 18;
        Wsrc = W_cs + (size_t)t * INC * HD;
        att  = attn_cs + (size_t)(t * 2 + 0) * HD;
        bvec = b_cs + (size_t)t * HD;
        dst  = g_wred_as_cs + t * INC * H; bdst = g_bred_as_cs + t * H;
    } else {
        int t = j - 21;
        Wsrc = W_in;
        att  = attn_cs + (size_t)(t * 2 + 1) * HD;
        bvec = b_in;
        dst  = g_wred_ad_s + t * INS * H; bdst = g_bred_ad_s + t * H;
        Kin = INS;
    }
    if (k >= Kin) return;
    float s = 0.f;
    #pragma unroll
    for (int d = 0; d < Dd; d++)
        s += Wsrc[(size_t)k * HD + h * Dd + d] * att[h * Dd + d];
    dst[k * H + h] = s;
    if (k == 0) {
        float bs = 0.f;
        #pragma unroll
        for (int d = 0; d < Dd; d++) bs += bvec[h * Dd + d] * att[h * Dd + d];
        bdst[h] = bs;
    }
}

// ---------------- fused skinny GEMMs: one pass over each node type ----------
__global__ void __launch_bounds__(256) k_skinny(const float* __restrict__ f1,
                                                const float* __restrict__ f2,
                                                const float* __restrict__ f3,
                                                const float* __restrict__ fs) {
    int t = blockIdx.y;
    __shared__ float Ws[7][H][INC];
    __shared__ float bsm[7][H];
    __shared__ const float* wptr[7];
    __shared__ float* optr[7];
    __shared__ const float* bptr[7];

    int Kin = (t < 3) ? INC : INS;
    int nG  = (t < 3) ? 7 : 3;
    int nNodes = (t < 3) ? NC : NS;
    const float* feat = (t == 0) ? f1 : (t == 1) ? f2 : (t == 2) ? f3 : fs;

    if (threadIdx.x < (unsigned)nG) {
        int g = threadIdx.x;
        if (t < 3) {
            if (g < 3) {
                int r = t * 3 + g;
                wptr[g] = g_wred_as + r * INC * H;
                bptr[g] = g_bred_as + r * H;
                optr[g] = g_as_cc + (size_t)r * NC * H;
            } else if (g < 6) {
                int r = (g - 3) * 3 + t;
                wptr[g] = g_wred_ad + r * INC * H;
                bptr[g] = g_bred_ad + r * H;
                optr[g] = g_ad_cc + (size_t)r * NC * H;
            } else {
                wptr[g] = g_wred_as_cs + t * INC * H;
                bptr[g] = g_bred_as_cs + t * H;
                optr[g] = g_as_cs + (size_t)t * NC * H;
            }
        } else {
            wptr[g] = g_wred_ad_s + g * INS * H;
            bptr[g] = g_bred_ad_s + g * H;
            optr[g] = g_ad_s + (size_t)g * NS * H;
        }
    }
    __syncthreads();

    for (int idx = threadIdx.x; idx < nG * H * Kin; idx += 256) {
        int g = idx / (H * Kin);
        int rem = idx % (H * Kin);
        int h = rem / Kin, k = rem % Kin;
        Ws[g][h][k] = wptr[g][k * H + h];
    }
    if (threadIdx.x < (unsigned)(nG * H)) {
        int g = threadIdx.x / H, h = threadIdx.x % H;
        bsm[g][h] = bptr[g][h];
    }
    __syncthreads();

    int warp = threadIdx.x >> 5, lane = threadIdx.x & 31;
    int node = blockIdx.x * 8 + warp;
    if (node >= nNodes) return;
    const float* frow = feat + (size_t)node * Kin;
    float f[4];
    int nc = Kin / 32;
    for (int c = 0; c < nc; c++) f[c] = frow[c * 32 + lane];

    for (int g = 0; g < nG; g++) {
        float mine = 0.f;
        #pragma unroll
        for (int h = 0; h < H; h++) {
            float v = 0.f;
            for (int c = 0; c < nc; c++) v += f[c] * Ws[g][h][c * 32 + lane];
            #pragma unroll
            for (int o = 16; o > 0; o >>= 1) v += __shfl_xor_sync(0xffffffffu, v, o);
            if (lane == h) mine = v;
        }
        if (lane < H) optr[g][(size_t)node * H + lane] = mine + bsm[g][lane];
    }
}

// ---------------- per-relation a_src max (for single-pass softmax) ----------
__global__ void __launch_bounds__(256) k_asmax() {
    int rel = blockIdx.x;
    const float* asb = (rel < 9) ? (g_as_cc + (size_t)rel * NC * H)
                                 : (g_as_cs + (size_t)(rel - 9) * NC * H);
    float mx[H];
    #pragma unroll
    for (int h = 0; h < H; h++) mx[h] = NEG_BIG;
    for (int i = threadIdx.x; i < NC; i += 256) {
        float4 a0 = *(const float4*)(asb + (size_t)i * H);
        float4 a1 = *(const float4*)(asb + (size_t)i * H + 4);
        mx[0]=fmaxf(mx[0],a0.x); mx[1]=fmaxf(mx[1],a0.y); mx[2]=fmaxf(mx[2],a0.z); mx[3]=fmaxf(mx[3],a0.w);
        mx[4]=fmaxf(mx[4],a1.x); mx[5]=fmaxf(mx[5],a1.y); mx[6]=fmaxf(mx[6],a1.z); mx[7]=fmaxf(mx[7],a1.w);
    }
    #pragma unroll
    for (int h = 0; h < H; h++)
        #pragma unroll
        for (int o = 16; o > 0; o >>= 1) mx[h] = fmaxf(mx[h], __shfl_xor_sync(0xffffffffu, mx[h], o));
    __shared__ float sm[8][H];
    int warp = threadIdx.x >> 5, lane = threadIdx.x & 31;
    if (lane == 0)
        #pragma unroll
        for (int h = 0; h < H; h++) sm[warp][h] = mx[h];
    __syncthreads();
    if (threadIdx.x < H) {
        float v = sm[0][threadIdx.x];
        #pragma unroll
        for (int w = 1; w < 8; w++) v = fmaxf(v, sm[w][threadIdx.x]);
        g_asmax[rel * H + threadIdx.x] = v;
    }
}

// ---------------- FP16 HMMA helper ----------------
__device__ __forceinline__ void mma_f16(float c[4], const unsigned a[4], const unsigned b[2]) {
    asm volatile("mma.sync.aligned.m16n8k16.row.col.f32.f16.f16.f32 "
        "{%0,%1,%2,%3}, {%4,%5,%6,%7}, {%8,%9}, {%0,%1,%2,%3};"
        : "+f"(c[0]), "+f"(c[1]), "+f"(c[2]), "+f"(c[3])
        : "r"(a[0]), "r"(a[1]), "r"(a[2]), "r"(a[3]), "r"(b[0]), "r"(b[1]));
}

// ---------------- big GEMMs: 13 jobs, FP16 HMMA m16n8k16, fp16 output ----------
__global__ void __launch_bounds__(256, 2) k_gemm(const float* __restrict__ f1, const float* __restrict__ f2,
                                                 const float* __restrict__ f3, const float* __restrict__ fs,
                                                 const float* __restrict__ Wcc, const float* __restrict__ bcc,
                                                 const float* __restrict__ Wcs, const float* __restrict__ bcs,
                                                 const float* __restrict__ Win, const float* __restrict__ bin) {
    int z = blockIdx.z;
    const float* A; const float* W; const float* bptr; __half* outp; int M, K;
    if (z < 9) {
        int s = z / 3;
        A = (s == 0) ? f1 : (s == 1) ? f2 : f3;
        W = Wcc + (size_t)z * INC * HD; bptr = bcc + (size_t)z * HD;
        outp = g_Wh_cc + (size_t)z * NC * HD; M = NC; K = INC;
    } else if (z < 12) {
        int t = z - 9;
        A = (t == 0) ? f1 : (t == 1) ? f2 : f3;
        W = Wcs + (size_t)t * INC * HD; bptr = bcs + (size_t)t * HD;
        outp = g_Wh_cs + (size_t)t * NC * HD; M = NC; K = INC;
    } else {
        A = fs; W = Win; bptr = bin; outp = g_Wh_in; M = NS; K = INS;
    }
    int row0 = blockIdx.x * 128;
    if (row0 >= M) return;
    int col0 = blockIdx.y * 128;

    __shared__ __half Ah[2][128][24];
    __shared__ __half Bh[2][128][24];

    int tid = threadIdx.x;
    int warp = tid >> 5, lane = tid & 31;
    int wm = warp & 3, wn = warp >> 2;
    int gr = lane >> 2, lc = lane & 3;

    int ar = tid >> 2, ak = (tid & 3) * 4;
    int br = tid >> 5, bc = (tid & 31) * 4;

    float4 la[2], lb[2];
    float c[2][8][4];
    #pragma unroll
    for (int mi = 0; mi < 2; mi++)
        #pragma unroll
        for (int ni = 0; ni < 8; ni++)
            #pragma unroll
            for (int q = 0; q < 4; q++) c[mi][ni][q] = 0.f;

    #pragma unroll
    for (int i = 0; i < 2; i++) {
        int r = ar + i * 64;
        la[i] = make_float4(0.f, 0.f, 0.f, 0.f);
        if (row0 + r < M) la[i] = *(const float4*)(A + (size_t)(row0 + r) * K + ak);
        lb[i] = *(const float4*)(W + (size_t)(br + i * 8) * HD + col0 + bc);
    }
    #pragma unroll
    for (int i = 0; i < 2; i++) {
        int r = ar + i * 64;
        Ah[0][r][ak + 0] = __float2half_rn(la[i].x); Ah[0][r][ak + 1] = __float2half_rn(la[i].y);
        Ah[0][r][ak + 2] = __float2half_rn(la[i].z); Ah[0][r][ak + 3] = __float2half_rn(la[i].w);
        int kk = br + i * 8;
        Bh[0][bc + 0][kk] = __float2half_rn(lb[i].x);
        Bh[0][bc + 1][kk] = __float2half_rn(lb[i].y);
        Bh[0][bc + 2][kk] = __float2half_rn(lb[i].z);
        Bh[0][bc + 3][kk] = __float2half_rn(lb[i].w);
    }
    __syncthreads();

    int nk = K / 16;
    for (int kc = 0; kc < nk; kc++) {
        int buf = kc & 1;
        bool nxt = (kc + 1) < nk;
        if (nxt) {
            int kt = (kc + 1) * 16;
            #pragma unroll
            for (int i = 0; i < 2; i++) {
                int r = ar + i * 64;
                la[i] = make_float4(0.f, 0.f, 0.f, 0.f);
                if (row0 + r < M) la[i] = *(const float4*)(A + (size_t)(row0 + r) * K + kt + ak);
                lb[i] = *(const float4*)(W + (size_t)(kt + br + i * 8) * HD + col0 + bc);
            }
        }
        {
            unsigned a[2][4], b[8][2];
            #pragma unroll
            for (int mi = 0; mi < 2; mi++) {
                int rb = wm * 32 + mi * 16 + gr;
                a[mi][0] = *(const unsigned*)&Ah[buf][rb][2 * lc];
                a[mi][1] = *(const unsigned*)&Ah[buf][rb + 8][2 * lc];
                a[mi][2] = *(const unsigned*)&Ah[buf][rb][2 * lc + 8];
                a[mi][3] = *(const unsigned*)&Ah[buf][rb + 8][2 * lc + 8];
            }
            #pragma unroll
            for (int ni = 0; ni < 8; ni++) {
                int cb = wn * 64 + ni * 8 + gr;
                b[ni][0] = *(const unsigned*)&Bh[buf][cb][2 * lc];
                b[ni][1] = *(const unsigned*)&Bh[buf][cb][2 * lc + 8];
            }
            #pragma unroll
            for (int mi = 0; mi < 2; mi++)
                #pragma unroll
                for (int ni = 0; ni < 8; ni++)
                    mma_f16(c[mi][ni], a[mi], b[ni]);
        }
        if (nxt) {
            int nb = buf ^ 1;
            #pragma unroll
            for (int i = 0; i < 2; i++) {
                int r = ar + i * 64;
                Ah[nb][r][ak + 0] = __float2half_rn(la[i].x); Ah[nb][r][ak + 1] = __float2half_rn(la[i].y);
                Ah[nb][r][ak + 2] = __float2half_rn(la[i].z); Ah[nb][r][ak + 3] = __float2half_rn(la[i].w);
                int kk = br + i * 8;
                Bh[nb][bc + 0][kk] = __float2half_rn(lb[i].x);
                Bh[nb][bc + 1][kk] = __float2half_rn(lb[i].y);
                Bh[nb][bc + 2][kk] = __float2half_rn(lb[i].z);
                Bh[nb][bc + 3][kk] = __float2half_rn(lb[i].w);
            }
        }
        __syncthreads();
    }

    #pragma unroll
    for (int mi = 0; mi < 2; mi++) {
        int r0 = row0 + wm * 32 + mi * 16 + gr;
        #pragma unroll
        for (int ni = 0; ni < 8; ni++) {
            int cl = col0 + wn * 64 + ni * 8 + lc * 2;
            float b0 = bptr[cl], b1 = bptr[cl + 1];
            if (r0 < M)
                *(__half2*)(outp + (size_t)r0 * HD + cl) =
                    __floats2half2_rn(c[mi][ni][0] + b0, c[mi][ni][1] + b1);
            if (r0 + 8 < M)
                *(__half2*)(outp + (size_t)(r0 + 8) * HD + cl) =
                    __floats2half2_rn(c[mi][ni][2] + b0, c[mi][ni][3] + b1);
        }
    }
}

// ---------------- CSR build: histogram, scan, scatter ----------------
__global__ void k_hist(const int* __restrict__ ecc_dst, const int* __restrict__ ecs_dst) {
    int gid = blockIdx.x * blockDim.x + threadIdx.x;
    if (gid < 9 * ECC) {
        int r = gid / ECC;
        atomicAdd(&g_cnt_cc[r * NC + ecc_dst[gid]], 1);
    } else if (gid < 9 * ECC + 3 * ECS) {
        int g = gid - 9 * ECC;
        int t = g / ECS;
        atomicAdd(&g_cnt_cs[t * NS + ecs_dst[g]], 1);
    }
}

__global__ void __launch_bounds__(1024) k_scan() {
    int rel = blockIdx.x;
    int n; int* cnt; int* off; int* cur;
    if (rel < 9) { n = NC; cnt = g_cnt_cc + rel * NC; off = g_off_cc + rel * NC; cur = g_cur_cc + rel * NC; }
    else { int t = rel - 9; n = NS; cnt = g_cnt_cs + t * NS; off = g_off_cs + t * NS; cur = g_cur_cs + t * NS; }
    int tid = threadIdx.x;
    int CH = (n + 1023) / 1024;
    int base = tid * CH;
    int loc[10]; int s = 0;
    for (int i = 0; i < CH; i++) {
        int v = (base + i < n) ? cnt[base + i] : 0;
        loc[i] = s; s += v;
    }
    __shared__ int sums[1024];
    sums[tid] = s; __syncthreads();
    for (int o = 1; o < 1024; o <<= 1) {
        int v = (tid >= o) ? sums[tid - o] : 0;
        __syncthreads();
        sums[tid] += v;
        __syncthreads();
    }
    int prefix = (tid == 0) ? 0 : sums[tid - 1];
    for (int i = 0; i < CH; i++) if (base + i < n) {
        int o2 = prefix + loc[i];
        off[base + i] = o2;
        cur[base + i] = o2;
    }
}

__global__ void k_scatter(const int* __restrict__ ecc_src, const int* __restrict__ ecc_dst,
                          const int* __restrict__ ecs_src, const int* __restrict__ ecs_dst) {
    int gid = blockIdx.x * blockDim.x + threadIdx.x;
    if (gid < 9 * ECC) {
        int r = gid / ECC;
        int pos = atomicAdd(&g_cur_cc[r * NC + ecc_dst[gid]], 1);
        g_csr_cc[r * ECC + pos] = ecc_src[gid];
    } else if (gid < 9 * ECC + 3 * ECS) {
        int g = gid - 9 * ECC;
        int t = g / ECS;
        int pos = atomicAdd(&g_cur_cs[t * NS + ecs_dst[g]], 1);
        g_csr_cs[t * ECS + pos] = ecs_src[g];
    }
}

// ---------------- fused single-pass softmax + gather ----------------
__device__ __forceinline__ float lrelu(float x) { return x > 0.f ? x : LALPHA * x; }

__device__ __forceinline__ float sel8(const float v[8], int hq) {
    float a = (hq & 1) ? v[1] : v[0];
    float b = (hq & 1) ? v[3] : v[2];
    float c = (hq & 1) ? v[5] : v[4];
    float d = (hq & 1) ? v[7] : v[6];
    float ab = (hq & 2) ? b : a;
    float cd = (hq & 2) ? d : c;
    return (hq & 4) ? cd : ab;
}

__device__ __forceinline__ void gat_relation(
    int lane, int warp, int hq, int beg, int cnt,
    const float* __restrict__ asb, const float* __restrict__ adp,
    const float* __restrict__ axp,
    const int* __restrict__ csr, const __half* __restrict__ Wh,
    float pbuf[8][32][H], int sbuf[8][32], float outacc[8])
{
    float ad[H], M[H];
    {
        float4 a0 = *(const float4*)adp;
        float4 a1 = *(const float4*)(adp + 4);
        float4 x0 = *(const float4*)axp;
        float4 x1 = *(const float4*)(axp + 4);
        ad[0]=a0.x; ad[1]=a0.y; ad[2]=a0.z; ad[3]=a0.w;
        ad[4]=a1.x; ad[5]=a1.y; ad[6]=a1.z; ad[7]=a1.w;
        M[0]=lrelu(x0.x+ad[0]); M[1]=lrelu(x0.y+ad[1]); M[2]=lrelu(x0.z+ad[2]); M[3]=lrelu(x0.w+ad[3]);
        M[4]=lrelu(x1.x+ad[4]); M[5]=lrelu(x1.y+ad[5]); M[6]=lrelu(x1.z+ad[6]); M[7]=lrelu(x1.w+ad[7]);
    }
    float lsum[H];
    #pragma unroll
    for (int h = 0; h < H; h++) lsum[h] = 0.f;
    float acc[8] = {};
    int nchunk = (cnt + 31) >> 5;
    for (int c = 0; c < nchunk; c++) {
        int e = c * 32 + lane;
        float p[H];
        int src = 0;
        if (e < cnt) {
            src = __ldg(&csr[beg + e]);
            float4 s0 = *(const float4*)(asb + (size_t)src * H);
            float4 s1 = *(const float4*)(asb + (size_t)src * H + 4);
            float ev[H];
            ev[0]=lrelu(s0.x+ad[0]); ev[1]=lrelu(s0.y+ad[1]); ev[2]=lrelu(s0.z+ad[2]); ev[3]=lrelu(s0.w+ad[3]);
            ev[4]=lrelu(s1.x+ad[4]); ev[5]=lrelu(s1.y+ad[5]); ev[6]=lrelu(s1.z+ad[6]); ev[7]=lrelu(s1.w+ad[7]);
            #pragma unroll
            for (int h = 0; h < H; h++) { p[h] = __expf(ev[h] - M[h]); lsum[h] += p[h]; }
        } else {
            #pragma unroll
            for (int h = 0; h < H; h++) p[h] = 0.f;
        }
        sbuf[warp][lane] = src;
        #pragma unroll
        for (int h = 0; h < H; h++) pbuf[warp][lane][h] = p[h];
        __syncwarp();
        int nv = min(32, cnt - c * 32);
        #pragma unroll 4
        for (int ee = 0; ee < nv; ee++) {
            int s2 = sbuf[warp][ee];
            float cf = pbuf[warp][ee][hq];
            uint4 u = *(const uint4*)(Wh + (size_t)s2 * HD + lane * 8);
            __half2 h0 = *(__half2*)&u.x, h1 = *(__half2*)&u.y;
            __half2 h2 = *(__half2*)&u.z, h3 = *(__half2*)&u.w;
            float2 f0 = __half22float2(h0), f1 = __half22float2(h1);
            float2 f2 = __half22float2(h2), f3 = __half22float2(h3);
            acc[0] += cf * f0.x; acc[1] += cf * f0.y;
            acc[2] += cf * f1.x; acc[3] += cf * f1.y;
            acc[4] += cf * f2.x; acc[5] += cf * f2.y;
            acc[6] += cf * f3.x; acc[7] += cf * f3.y;
        }
        __syncwarp();
    }
    #pragma unroll
    for (int h = 0; h < H; h++)
        #pragma unroll
        for (int o = 16; o > 0; o >>= 1) lsum[h] += __shfl_xor_sync(0xffffffffu, lsum[h], o);
    float invs = 1.f / sel8(lsum, hq);
    #pragma unroll
    for (int j = 0; j < 8; j++) outacc[j] += acc[j] * invs;
}

// merged gather: y = 0..2 -> C dst types, y = 3 -> state nodes.
// Bodies are verbatim from the champion's k_gather_cc / k_gather_state
// (per-relation sequential, no interleaving).
__global__ void __launch_bounds__(256) k_gather(float* __restrict__ out) {
    __shared__ float pbuf[8][32][H];
    __shared__ int   sbuf[8][32];
    int y = blockIdx.y;
    int warp = threadIdx.x >> 5, lane = threadIdx.x & 31;
    int node = blockIdx.x * 8 + warp;
    int hq = lane >> 2;

    if (y < 3) {
        if (node >= NC) return;
        int dt = y;
        float outacc[8] = {};
        #pragma unroll 1
        for (int s = 0; s < 3; s++) {
            int r = 3 * s + dt;
            int beg = g_off_cc[r * NC + node];
            int cnt = g_cnt_cc[r * NC + node];
            if (cnt == 0) continue;
            gat_relation(lane, warp, hq, beg, cnt,
                         g_as_cc + (size_t)r * NC * H,
                         g_ad_cc + ((size_t)r * NC + node) * H,
                         g_asmax + r * H,
                         g_csr_cc + (size_t)r * ECC,
                         g_Wh_cc + (size_t)r * NC * HD,
                         pbuf, sbuf, outacc);
        }
        float* o = out + ((size_t)dt * NC + node) * HD + lane * 8;
        float4 v0, v1;
        v0.x = fmaxf(outacc[0], 0.f); v0.y = fmaxf(outacc[1], 0.f);
        v0.z = fmaxf(outacc[2], 0.f); v0.w = fmaxf(outacc[3], 0.f);
        v1.x = fmaxf(outacc[4], 0.f); v1.y = fmaxf(outacc[5], 0.f);
        v1.z = fmaxf(outacc[6], 0.f); v1.w = fmaxf(outacc[7], 0.f);
        *(float4*)o = v0; *(float4*)(o + 4) = v1;
    } else {
        if (node >= NS) return;
        float outacc[8] = {};
        {   // self term
            uint4 u = *(const uint4*)(g_Wh_in + (size_t)node * HD + lane * 8);
            __half2 h0 = *(__half2*)&u.x, h1 = *(__half2*)&u.y;
            __half2 h2 = *(__half2*)&u.z, h3 = *(__half2*)&u.w;
            float2 f0 = __half22float2(h0), f1 = __half22float2(h1);
            float2 f2 = __half22float2(h2), f3 = __half22float2(h3);
            outacc[0]=f0.x; outacc[1]=f0.y; outacc[2]=f1.x; outacc[3]=f1.y;
            outacc[4]=f2.x; outacc[5]=f2.y; outacc[6]=f3.x; outacc[7]=f3.y;
        }
        #pragma unroll 1
        for (int t = 0; t < 3; t++) {
            int beg = g_off_cs[t * NS + node];
            int cnt = g_cnt_cs[t * NS + node];
            if (cnt == 0) continue;
            gat_relation(lane, warp, hq, beg, cnt,
                         g_as_cs + (size_t)t * NC * H,
                         g_ad_s + ((size_t)t * NS + node) * H,
                         g_asmax + (9 + t) * H,
                         g_csr_cs + (size_t)t * ECS,
                         g_Wh_cs + (size_t)t * NC * HD,
                         pbuf, sbuf, outacc);
        }
        float* o = out + (size_t)3 * NC * HD + (size_t)node * HD + lane * 8;
        float4 v0, v1;
        v0.x = fmaxf(outacc[0], 0.f); v0.y = fmaxf(outacc[1], 0.f);
        v0.z = fmaxf(outacc[2], 0.f); v0.w = fmaxf(outacc[3], 0.f);
        v1.x = fmaxf(outacc[4], 0.f); v1.y = fmaxf(outacc[5], 0.f);
        v1.z = fmaxf(outacc[6], 0.f); v1.w = fmaxf(outacc[7], 0.f);
        *(float4*)o = v0; *(float4*)(o + 4) = v1;
    }
}

// ---------------- launch: fork/join two independent chains ----------------
static cudaStream_t g_s1 = 0;
static cudaEvent_t g_evFork = 0, g_evCsr = 0;

extern "C" void kernel_launch(void* const* d_in, const int* in_sizes, int n_in,
                              void* d_out, int out_size) {
    const float* f1      = (const float*)d_in[0];
    const float* f2      = (const float*)d_in[1];
    const float* f3      = (const float*)d_in[2];
    const float* fs      = (const float*)d_in[3];
    const float* W_node  = (const float*)d_in[4];
    const float* b_node  = (const float*)d_in[5];
    const float* W_cc    = (const float*)d_in[6];
    const float* b_cc    = (const float*)d_in[7];
    const float* W_cs    = (const float*)d_in[8];
    const float* b_cs    = (const float*)d_in[9];
    const float* W_in    = (const float*)d_in[10];
    const float* b_in    = (const float*)d_in[11];
    const float* attn_cc = (const float*)d_in[12];
    const float* attn_cs = (const float*)d_in[13];
    const int* ecc_src   = (const int*)d_in[14];
    const int* ecc_dst   = (const int*)d_in[15];
    const int* ecs_src   = (const int*)d_in[16];
    const int* ecs_dst   = (const int*)d_in[17];
    float* out = (float*)d_out;

    if (!g_s1) {   // lazy init on first (uncaptured) call; no device memory allocated
        cudaStreamCreateWithFlags(&g_s1, cudaStreamNonBlocking);
        cudaEventCreateWithFlags(&g_evFork, cudaEventDisableTiming);
        cudaEventCreateWithFlags(&g_evCsr, cudaEventDisableTiming);
    }

    int tot = 9 * ECC + 3 * ECS;

    // fork: CSR chain on s1 (depends only on edge lists)
    cudaEventRecord(g_evFork, 0);
    cudaStreamWaitEvent(g_s1, g_evFork, 0);
    k_zero_counters<<<(9 * NC + 255) / 256, 256, 0, g_s1>>>();
    k_hist<<<(tot + 255) / 256, 256, 0, g_s1>>>(ecc_dst, ecs_dst);
    k_scan<<<12, 1024, 0, g_s1>>>();
    k_scatter<<<(tot + 255) / 256, 256, 0, g_s1>>>(ecc_src, ecc_dst, ecs_src, ecs_dst);
    cudaEventRecord(g_evCsr, g_s1);

    // main stream: projection chain
    k_wred<<<(24 * INC * H + 255) / 256, 256>>>(W_node, b_node, W_cc, b_cc, W_cs, b_cs, W_in, b_in, attn_cc, attn_cs);
    k_skinny<<<dim3(1250, 4), 256>>>(f1, f2, f3, fs);
    k_asmax<<<12, 256>>>();
    k_gemm<<<dim3(79, 2, 13), 256>>>(f1, f2, f3, fs, W_cc, b_cc, W_cs, b_cs, W_in, b_in);

    // join CSR, then single merged gather (C types + state)
    cudaStreamWaitEvent(0, g_evCsr, 0);
    k_gather<<<dim3(1250, 4), 256>>>(out);
}